// round 1
// baseline (speedup 1.0000x reference)
#include <cuda_runtime.h>

// Problem constants
#define BB 32
#define NN 2048
#define DD 128
#define HH 8
#define KQ 64

// Scratch (no cudaMalloc allowed)
__device__ float g_S[BB * DD * DD];   // per-batch Gram matrices x_b^T x_b
__device__ float g_M[BB * DD * DD];   // per-batch combined matrices

// -------------------------------------------------------------------------
// Kernel 0: zero the accumulators
// grid 512 x 256 threads, each zeroes one float4 in each array
__global__ void zero_kernel() {
    int idx = blockIdx.x * blockDim.x + threadIdx.x;  // < 131072
    float4 z = make_float4(0.f, 0.f, 0.f, 0.f);
    ((float4*)g_S)[idx] = z;
    ((float4*)g_M)[idx] = z;
}

// -------------------------------------------------------------------------
// Kernel 1: S_b += x_chunk^T x_chunk  (chunk = 128 rows of n)
// grid (16, 32), 256 threads (16x16), each thread an 8x8 tile of the 128x128 output
__global__ __launch_bounds__(256) void gram_kernel(const float* __restrict__ x) {
    __shared__ float sx[16 * 128];
    const int b = blockIdx.y;
    const int n0 = blockIdx.x * 128;
    const int tid = threadIdx.x;
    const int tx = tid & 15, ty = tid >> 4;
    const int i0 = ty * 8, j0 = tx * 8;

    float acc[8][8];
#pragma unroll
    for (int i = 0; i < 8; i++)
#pragma unroll
        for (int j = 0; j < 8; j++) acc[i][j] = 0.f;

    const float4* xb = (const float4*)(x + ((size_t)b * NN + n0) * DD);

    for (int ks = 0; ks < 128; ks += 16) {
        // load 16 n-rows x 128 d into smem (512 float4s)
        ((float4*)sx)[tid]       = xb[ks * 32 + tid];
        ((float4*)sx)[tid + 256] = xb[ks * 32 + tid + 256];
        __syncthreads();
#pragma unroll
        for (int kk = 0; kk < 16; ++kk) {
            float a[8], c[8];
            *(float4*)(a)     = *(const float4*)&sx[kk * 128 + i0];
            *(float4*)(a + 4) = *(const float4*)&sx[kk * 128 + i0 + 4];
            *(float4*)(c)     = *(const float4*)&sx[kk * 128 + j0];
            *(float4*)(c + 4) = *(const float4*)&sx[kk * 128 + j0 + 4];
#pragma unroll
            for (int i = 0; i < 8; i++)
#pragma unroll
                for (int j = 0; j < 8; j++) acc[i][j] += a[i] * c[j];
        }
        __syncthreads();
    }

    float* Sb = g_S + b * DD * DD;
#pragma unroll
    for (int i = 0; i < 8; i++)
#pragma unroll
        for (int j = 0; j < 8; j++)
            atomicAdd(&Sb[(i0 + i) * DD + (j0 + j)], acc[i][j]);
}

// -------------------------------------------------------------------------
// Kernel 2: per (b,h): tmp1 = Wk_h S_b ; tmp2 = tmp1 Wv_h^T ; M_b += Wq_h^T tmp2
// grid (8, 32), 256 threads. Dynamic smem: buf0 (128*68) + buf1 (128*132) floats.
#define ST_KT 68    // padded row stride for transposed [d][k] buffers
#define ST_VT 132   // padded row stride for transposed [d][e] Wv buffer
#define BUF0_F (128 * ST_KT)   // 8704 floats
#define BUF1_F (128 * ST_VT)   // 16896 floats
#define MID_SMEM_BYTES ((BUF0_F + BUF1_F) * 4)

__global__ __launch_bounds__(256) void mid_kernel(const float* __restrict__ Wk,
                                                  const float* __restrict__ Wq,
                                                  const float* __restrict__ Wv) {
    extern __shared__ float smem[];
    float* buf0 = smem;            // WkT -> tmp1T -> tmp2
    float* buf1 = smem + BUF0_F;   // S -> WvT -> Wq

    const int h = blockIdx.x, b = blockIdx.y;
    const int tid = threadIdx.x;

    // Load Wk_h transposed: buf0[d*68 + k] = Wk[h,k,d]
    const float* Wkh = Wk + h * KQ * DD;
    for (int idx = tid; idx < KQ * DD; idx += 256) {
        int k = idx >> 7, d = idx & 127;
        buf0[d * ST_KT + k] = Wkh[idx];
    }
    // Load S_b row-major (stride 128)
    const float4* Sb4 = (const float4*)(g_S + b * DD * DD);
    for (int i = tid; i < DD * DD / 4; i += 256) ((float4*)buf1)[i] = Sb4[i];
    __syncthreads();

    const int ty = tid >> 5, tx = tid & 31;
    const int r0 = ty * 8, c0 = tx * 4;   // r0: k rows, c0: d'/e cols

    // ---- Stage 1: tmp1[k,d'] = sum_d Wk[k,d] * S[d,d']
    float acc1[8][4];
#pragma unroll
    for (int i = 0; i < 8; i++)
#pragma unroll
        for (int j = 0; j < 4; j++) acc1[i][j] = 0.f;
#pragma unroll 4
    for (int d = 0; d < 128; ++d) {
        float a[8], c[4];
        *(float4*)(a)     = *(const float4*)&buf0[d * ST_KT + r0];
        *(float4*)(a + 4) = *(const float4*)&buf0[d * ST_KT + r0 + 4];
        *(float4*)(c)     = *(const float4*)&buf1[d * 128 + c0];
#pragma unroll
        for (int i = 0; i < 8; i++)
#pragma unroll
            for (int j = 0; j < 4; j++) acc1[i][j] += a[i] * c[j];
    }
    __syncthreads();  // everyone done reading buf0/buf1

    // Write tmp1 transposed into buf0: tmp1T[d'][k]
#pragma unroll
    for (int j = 0; j < 4; j++) {
        *(float4*)&buf0[(c0 + j) * ST_KT + r0] =
            make_float4(acc1[0][j], acc1[1][j], acc1[2][j], acc1[3][j]);
        *(float4*)&buf0[(c0 + j) * ST_KT + r0 + 4] =
            make_float4(acc1[4][j], acc1[5][j], acc1[6][j], acc1[7][j]);
    }
    // Load Wv_h transposed: buf1[d*132 + e] = Wv[h,e,d]
    const float* Wvh = Wv + h * DD * DD;
    for (int idx = tid; idx < DD * DD; idx += 256) {
        int e = idx >> 7, d = idx & 127;
        buf1[d * ST_VT + e] = Wvh[idx];
    }
    __syncthreads();

    // ---- Stage 2: tmp2[k,e] = sum_d' tmp1T[d'][k] * WvT[d'][e]
    float acc2[8][4];
#pragma unroll
    for (int i = 0; i < 8; i++)
#pragma unroll
        for (int j = 0; j < 4; j++) acc2[i][j] = 0.f;
#pragma unroll 4
    for (int d = 0; d < 128; ++d) {
        float a[8], c[4];
        *(float4*)(a)     = *(const float4*)&buf0[d * ST_KT + r0];
        *(float4*)(a + 4) = *(const float4*)&buf0[d * ST_KT + r0 + 4];
        *(float4*)(c)     = *(const float4*)&buf1[d * ST_VT + c0];
#pragma unroll
        for (int i = 0; i < 8; i++)
#pragma unroll
            for (int j = 0; j < 4; j++) acc2[i][j] += a[i] * c[j];
    }
    __syncthreads();

    // Write tmp2 row-major [k][e] into buf0
#pragma unroll
    for (int i = 0; i < 8; i++)
        *(float4*)&buf0[(r0 + i) * 128 + c0] =
            make_float4(acc2[i][0], acc2[i][1], acc2[i][2], acc2[i][3]);
    // Load Wq_h row-major [k][d] into buf1
    const float* Wqh = Wq + h * KQ * DD;
    for (int i = tid; i < KQ * DD / 4; i += 256)
        ((float4*)buf1)[i] = ((const float4*)Wqh)[i];
    __syncthreads();

    // ---- Stage 3: M_b[d,e] += sum_k Wq[k][d] * tmp2[k][e]
    const int tx16 = tid & 15, ty16 = tid >> 4;
    const int d0 = ty16 * 8, e0 = tx16 * 8;
    float acc3[8][8];
#pragma unroll
    for (int i = 0; i < 8; i++)
#pragma unroll
        for (int j = 0; j < 8; j++) acc3[i][j] = 0.f;
#pragma unroll 4
    for (int k = 0; k < 64; ++k) {
        float a[8], c[8];
        *(float4*)(a)     = *(const float4*)&buf1[k * 128 + d0];
        *(float4*)(a + 4) = *(const float4*)&buf1[k * 128 + d0 + 4];
        *(float4*)(c)     = *(const float4*)&buf0[k * 128 + e0];
        *(float4*)(c + 4) = *(const float4*)&buf0[k * 128 + e0 + 4];
#pragma unroll
        for (int i = 0; i < 8; i++)
#pragma unroll
            for (int j = 0; j < 8; j++) acc3[i][j] += a[i] * c[j];
    }
    float* Mb = g_M + b * DD * DD;
#pragma unroll
    for (int i = 0; i < 8; i++)
#pragma unroll
        for (int j = 0; j < 8; j++)
            atomicAdd(&Mb[(d0 + i) * DD + (e0 + j)], acc3[i][j]);
}

// -------------------------------------------------------------------------
// Kernel 3: out[b, n0:n0+128, :] = x[b, n0:n0+128, :] @ M_b
// grid (16, 32), 256 threads (16x16), each thread 8x8. Dynamic smem 133120 B.
#define OUT_SMEM_F (16384 + 128 * ST_VT)
#define OUT_SMEM_BYTES (OUT_SMEM_F * 4)

__global__ __launch_bounds__(256) void out_kernel(const float* __restrict__ x,
                                                  float* __restrict__ out) {
    extern __shared__ float smem[];
    float* sM  = smem;           // 128x128 row-major
    float* sxT = smem + 16384;   // x chunk transposed [d][n], stride 132

    const int b = blockIdx.y;
    const int n0 = blockIdx.x * 128;
    const int tid = threadIdx.x;

    // Load M_b
    const float4* Mb4 = (const float4*)(g_M + b * DD * DD);
    for (int i = tid; i < DD * DD / 4; i += 256) ((float4*)sM)[i] = Mb4[i];
    // Load x chunk transposed
    const float* xb = x + ((size_t)b * NN + n0) * DD;
    for (int idx = tid; idx < 128 * DD; idx += 256) {
        int n = idx >> 7, d = idx & 127;
        sxT[d * ST_VT + n] = xb[idx];
    }
    __syncthreads();

    const int tx16 = tid & 15, ty16 = tid >> 4;
    const int nl0 = ty16 * 8, e0 = tx16 * 8;
    float acc[8][8];
#pragma unroll
    for (int i = 0; i < 8; i++)
#pragma unroll
        for (int j = 0; j < 8; j++) acc[i][j] = 0.f;

#pragma unroll 4
    for (int d = 0; d < 128; ++d) {
        float a[8], c[8];
        *(float4*)(a)     = *(const float4*)&sxT[d * ST_VT + nl0];
        *(float4*)(a + 4) = *(const float4*)&sxT[d * ST_VT + nl0 + 4];
        *(float4*)(c)     = *(const float4*)&sM[d * 128 + e0];
        *(float4*)(c + 4) = *(const float4*)&sM[d * 128 + e0 + 4];
#pragma unroll
        for (int i = 0; i < 8; i++)
#pragma unroll
            for (int j = 0; j < 8; j++) acc[i][j] += a[i] * c[j];
    }

    float* ob = out + ((size_t)b * NN + n0) * DD;
#pragma unroll
    for (int i = 0; i < 8; i++) {
        *(float4*)&ob[(nl0 + i) * DD + e0] =
            make_float4(acc[i][0], acc[i][1], acc[i][2], acc[i][3]);
        *(float4*)&ob[(nl0 + i) * DD + e0 + 4] =
            make_float4(acc[i][4], acc[i][5], acc[i][6], acc[i][7]);
    }
}

// -------------------------------------------------------------------------
extern "C" void kernel_launch(void* const* d_in, const int* in_sizes, int n_in,
                              void* d_out, int out_size) {
    const float* x  = (const float*)d_in[0];  // [32, 2048, 128]
    const float* Wk = (const float*)d_in[1];  // [8, 64, 128]
    const float* Wq = (const float*)d_in[2];  // [8, 64, 128]
    const float* Wv = (const float*)d_in[3];  // [8, 128, 128]
    float* out = (float*)d_out;               // [32, 2048, 128]

    cudaFuncSetAttribute(mid_kernel, cudaFuncAttributeMaxDynamicSharedMemorySize,
                         MID_SMEM_BYTES);
    cudaFuncSetAttribute(out_kernel, cudaFuncAttributeMaxDynamicSharedMemorySize,
                         OUT_SMEM_BYTES);

    zero_kernel<<<512, 256>>>();
    gram_kernel<<<dim3(16, 32), 256>>>(x);
    mid_kernel<<<dim3(8, 32), 256, MID_SMEM_BYTES>>>(Wk, Wq, Wv);
    out_kernel<<<dim3(16, 32), 256, OUT_SMEM_BYTES>>>(x, out);
}

// round 3
// speedup vs baseline: 1.4291x; 1.4291x over previous
#include <cuda_runtime.h>
#include <cuda_bf16.h>
#include <cstdint>

// Problem constants
#define BB 32
#define NN 2048
#define DD 128
#define HH 8
#define KQ 64
#define NSPLIT 8

// ------------------------------------------------------------------ scratch
__device__ float g_Spart[NSPLIT * BB * DD * DD];    // gram partials per split
__device__ float g_Mpart[HH * BB * DD * DD];        // M partials per head
__device__ __nv_bfloat16 g_xnd_hi[BB * NN * DD];    // x hi, [b][n][d]
__device__ __nv_bfloat16 g_xnd_lo[BB * NN * DD];
__device__ __nv_bfloat16 g_xdn_hi[BB * DD * NN];    // x hi, [b][d][n]
__device__ __nv_bfloat16 g_xdn_lo[BB * DD * NN];
__device__ __nv_bfloat16 g_MT_hi[BB * DD * DD];     // M^T hi, [b][e][d]
__device__ __nv_bfloat16 g_MT_lo[BB * DD * DD];

// ------------------------------------------------------------------ helpers
__device__ __forceinline__ uint32_t smem_u32(const void* p) {
    uint32_t a;
    asm("{ .reg .u64 t; cvta.to.shared.u64 t, %1; cvt.u32.u64 %0, t; }"
        : "=r"(a) : "l"(p));
    return a;
}

#define CP_ASYNC16(saddr, gptr) \
    asm volatile("cp.async.cg.shared.global [%0], [%1], 16;" \
                 :: "r"(saddr), "l"(gptr) : "memory")
#define CP_ASYNC_COMMIT() asm volatile("cp.async.commit_group;" ::: "memory")
#define CP_ASYNC_WAIT0()  asm volatile("cp.async.wait_group 0;" ::: "memory")
#define CP_ASYNC_WAIT1()  asm volatile("cp.async.wait_group 1;" ::: "memory")

__device__ __forceinline__ void ldsm4(uint32_t* r, uint32_t addr) {
    asm volatile("ldmatrix.sync.aligned.m8n8.x4.shared.b16 {%0,%1,%2,%3}, [%4];"
                 : "=r"(r[0]), "=r"(r[1]), "=r"(r[2]), "=r"(r[3]) : "r"(addr));
}

__device__ __forceinline__ void mma_bf16(float* d, const uint32_t* a,
                                         uint32_t b0, uint32_t b1) {
    asm volatile(
        "mma.sync.aligned.m16n8k16.row.col.f32.bf16.bf16.f32 "
        "{%0,%1,%2,%3}, {%4,%5,%6,%7}, {%8,%9}, {%0,%1,%2,%3};"
        : "+f"(d[0]), "+f"(d[1]), "+f"(d[2]), "+f"(d[3])
        : "r"(a[0]), "r"(a[1]), "r"(a[2]), "r"(a[3]), "r"(b0), "r"(b1));
}

// ==========================================================================
// Kernel 1: x fp32 -> hi/lo bf16 in [b][n][d] and transposed [b][d][n]
#define CONV_SMEM_BYTES (2 * 128 * 132 * 2)
__global__ __launch_bounds__(256) void convert_x(const float* __restrict__ x) {
    extern __shared__ __align__(128) char smraw[];
    __nv_bfloat16* sh = (__nv_bfloat16*)smraw;        // [d][n] hi
    __nv_bfloat16* sl = sh + 128 * 132;

    const int b = blockIdx.y, n0 = blockIdx.x * 128;
    const int tid = threadIdx.x;
    const float4* xt = (const float4*)(x + ((size_t)b * NN + n0) * DD);

    for (int i = tid; i < 4096; i += 256) {
        int n = i >> 5, p = i & 31;          // p*4 = starting d
        float4 v = xt[i];
        __nv_bfloat16 h[4], l[4];
        float vv[4] = {v.x, v.y, v.z, v.w};
#pragma unroll
        for (int j = 0; j < 4; j++) {
            h[j] = __float2bfloat16(vv[j]);
            l[j] = __float2bfloat16(vv[j] - __bfloat162float(h[j]));
        }
        size_t gi = ((size_t)b * NN + n0 + n) * DD + p * 4;
        *(uint2*)(g_xnd_hi + gi) = *(uint2*)h;
        *(uint2*)(g_xnd_lo + gi) = *(uint2*)l;
#pragma unroll
        for (int j = 0; j < 4; j++) {
            sh[(p * 4 + j) * 132 + n] = h[j];
            sl[(p * 4 + j) * 132 + n] = l[j];
        }
    }
    __syncthreads();
    for (int i = tid; i < 4096; i += 256) {
        int d = i >> 5, c = i & 31;
        __nv_bfloat16 th[4], tl[4];
#pragma unroll
        for (int j = 0; j < 4; j++) {
            th[j] = sh[d * 132 + c * 4 + j];
            tl[j] = sl[d * 132 + c * 4 + j];
        }
        size_t gi = ((size_t)b * DD + d) * NN + n0 + c * 4;
        *(uint2*)(g_xdn_hi + gi) = *(uint2*)th;
        *(uint2*)(g_xdn_lo + gi) = *(uint2*)tl;
    }
}

// ==========================================================================
// Kernel 2: Gram partials via mma.sync.  grid (NSPLIT, 32), 256 threads.
// CTA computes Spart[split][b] = x[:, nrange]^T x[:, nrange], nrange = 256.
// smem: 2 stages x (hi,lo) tiles of [128 d][64 n] bf16, row stride 72 elems.
#define SKT 72
#define GTILE_B (128 * SKT * 2)          // 18432
#define GRAM_SMEM_BYTES (4 * GTILE_B)    // 73728
__global__ __launch_bounds__(256, 1) void gram_mma() {
    extern __shared__ __align__(128) char sm[];
    uint32_t sb = smem_u32(sm);
    const int b = blockIdx.y, split = blockIdx.x;
    const int nbase = split * 256;
    const int tid = threadIdx.x, lane = tid & 31, wid = tid >> 5;
    const int m0 = (wid & 1) * 64, n0 = (wid >> 1) * 32;

    const __nv_bfloat16* gh = g_xdn_hi + (size_t)b * DD * NN;
    const __nv_bfloat16* gl = g_xdn_lo + (size_t)b * DD * NN;

    float acc[4][4][4];
#pragma unroll
    for (int mi = 0; mi < 4; mi++)
#pragma unroll
        for (int nj = 0; nj < 4; nj++)
#pragma unroll
            for (int q = 0; q < 4; q++) acc[mi][nj][q] = 0.f;

    // issue loads for chunk c into stage c&1
#define GRAM_ISSUE(c)                                                          \
    do {                                                                       \
        int st_ = (c) & 1;                                                     \
        int nc_ = nbase + (c) * 64;                                            \
        uint32_t th_ = sb + (st_ * 2) * GTILE_B;                               \
        uint32_t tl_ = th_ + GTILE_B;                                          \
        for (int i = tid; i < 1024; i += 256) {                                \
            int row = i >> 3, seg = i & 7;                                     \
            uint32_t off = row * 144 + seg * 16;                               \
            CP_ASYNC16(th_ + off, gh + row * NN + nc_ + seg * 8);              \
            CP_ASYNC16(tl_ + off, gl + row * NN + nc_ + seg * 8);              \
        }                                                                      \
        CP_ASYNC_COMMIT();                                                     \
    } while (0)

    GRAM_ISSUE(0);
    for (int c = 0; c < 4; c++) {
        if (c + 1 < 4) { GRAM_ISSUE(c + 1); CP_ASYNC_WAIT1(); }
        else           { CP_ASYNC_WAIT0(); }
        __syncthreads();
        uint32_t th = sb + ((c & 1) * 2) * GTILE_B;
        uint32_t tl = th + GTILE_B;
#pragma unroll
        for (int ko = 0; ko < 64; ko += 16) {
            uint32_t Ah[4][4], Al[4][4], Bh[2][4], Bl[2][4];
            const int arow = lane & 15;
            const int acolB = (ko + (lane >> 4) * 8) * 2;
#pragma unroll
            for (int mi = 0; mi < 4; mi++) {
                uint32_t o = (m0 + mi * 16 + arow) * 144 + acolB;
                ldsm4(Ah[mi], th + o);
                ldsm4(Al[mi], tl + o);
            }
#pragma unroll
            for (int njp = 0; njp < 2; njp++) {
                uint32_t o = (n0 + njp * 16 + arow) * 144 + acolB;
                ldsm4(Bh[njp], th + o);
                ldsm4(Bl[njp], tl + o);
            }
#pragma unroll
            for (int mi = 0; mi < 4; mi++)
#pragma unroll
                for (int nj = 0; nj < 4; nj++) {
                    int njp = nj >> 1, odd = nj & 1;
                    uint32_t bh0 = Bh[njp][odd], bh1 = Bh[njp][odd + 2];
                    uint32_t bl0 = Bl[njp][odd], bl1 = Bl[njp][odd + 2];
                    mma_bf16(acc[mi][nj], Ah[mi], bh0, bh1);
                    mma_bf16(acc[mi][nj], Ah[mi], bl0, bl1);
                    mma_bf16(acc[mi][nj], Al[mi], bh0, bh1);
                }
        }
        __syncthreads();
    }

    float* Sp = g_Spart + (size_t)(split * BB + b) * (DD * DD);
    const int g = lane >> 2, t = lane & 3;
#pragma unroll
    for (int mi = 0; mi < 4; mi++)
#pragma unroll
        for (int nj = 0; nj < 4; nj++) {
            int r = m0 + mi * 16 + g, cc = n0 + nj * 8 + t * 2;
            *(float2*)&Sp[r * DD + cc] =
                make_float2(acc[mi][nj][0], acc[mi][nj][1]);
            *(float2*)&Sp[(r + 8) * DD + cc] =
                make_float2(acc[mi][nj][2], acc[mi][nj][3]);
        }
}

// ==========================================================================
// Kernel 3: per (b,h): Mpart[h][b] = Wq_h^T (Wk_h (sum_p Spart)) Wv_h^T
#define ST_KT 68
#define ST_VT 132
#define BUF0_F (128 * ST_KT)
#define BUF1_F (128 * ST_VT)
#define MID_SMEM_BYTES ((BUF0_F + BUF1_F) * 4)

__global__ __launch_bounds__(256) void mid_kernel(const float* __restrict__ Wk,
                                                  const float* __restrict__ Wq,
                                                  const float* __restrict__ Wv) {
    extern __shared__ float smem[];
    float* buf0 = smem;
    float* buf1 = smem + BUF0_F;
    const int h = blockIdx.x, b = blockIdx.y;
    const int tid = threadIdx.x;

    const float* Wkh = Wk + h * KQ * DD;
    for (int idx = tid; idx < KQ * DD; idx += 256) {
        int k = idx >> 7, d = idx & 127;
        buf0[d * ST_KT + k] = Wkh[idx];
    }
    // S = sum of split partials
    for (int i = tid; i < DD * DD / 4; i += 256) {
        float4 s = make_float4(0.f, 0.f, 0.f, 0.f);
#pragma unroll
        for (int p = 0; p < NSPLIT; p++) {
            float4 v = ((const float4*)(g_Spart + (size_t)(p * BB + b) * DD * DD))[i];
            s.x += v.x; s.y += v.y; s.z += v.z; s.w += v.w;
        }
        ((float4*)buf1)[i] = s;
    }
    __syncthreads();

    const int ty = tid >> 5, tx = tid & 31;
    const int r0 = ty * 8, c0 = tx * 4;

    float acc1[8][4];
#pragma unroll
    for (int i = 0; i < 8; i++)
#pragma unroll
        for (int j = 0; j < 4; j++) acc1[i][j] = 0.f;
#pragma unroll 4
    for (int d = 0; d < 128; ++d) {
        float a[8], c[4];
        *(float4*)(a)     = *(const float4*)&buf0[d * ST_KT + r0];
        *(float4*)(a + 4) = *(const float4*)&buf0[d * ST_KT + r0 + 4];
        *(float4*)(c)     = *(const float4*)&buf1[d * 128 + c0];
#pragma unroll
        for (int i = 0; i < 8; i++)
#pragma unroll
            for (int j = 0; j < 4; j++) acc1[i][j] += a[i] * c[j];
    }
    __syncthreads();

#pragma unroll
    for (int j = 0; j < 4; j++) {
        *(float4*)&buf0[(c0 + j) * ST_KT + r0] =
            make_float4(acc1[0][j], acc1[1][j], acc1[2][j], acc1[3][j]);
        *(float4*)&buf0[(c0 + j) * ST_KT + r0 + 4] =
            make_float4(acc1[4][j], acc1[5][j], acc1[6][j], acc1[7][j]);
    }
    const float* Wvh = Wv + h * DD * DD;
    for (int idx = tid; idx < DD * DD; idx += 256) {
        int e = idx >> 7, d = idx & 127;
        buf1[d * ST_VT + e] = Wvh[idx];
    }
    __syncthreads();

    float acc2[8][4];
#pragma unroll
    for (int i = 0; i < 8; i++)
#pragma unroll
        for (int j = 0; j < 4; j++) acc2[i][j] = 0.f;
#pragma unroll 4
    for (int d = 0; d < 128; ++d) {
        float a[8], c[4];
        *(float4*)(a)     = *(const float4*)&buf0[d * ST_KT + r0];
        *(float4*)(a + 4) = *(const float4*)&buf0[d * ST_KT + r0 + 4];
        *(float4*)(c)     = *(const float4*)&buf1[d * ST_VT + c0];
#pragma unroll
        for (int i = 0; i < 8; i++)
#pragma unroll
            for (int j = 0; j < 4; j++) acc2[i][j] += a[i] * c[j];
    }
    __syncthreads();

#pragma unroll
    for (int i = 0; i < 8; i++)
        *(float4*)&buf0[(r0 + i) * 128 + c0] =
            make_float4(acc2[i][0], acc2[i][1], acc2[i][2], acc2[i][3]);
    const float* Wqh = Wq + h * KQ * DD;
    for (int i = tid; i < KQ * DD / 4; i += 256)
        ((float4*)buf1)[i] = ((const float4*)Wqh)[i];
    __syncthreads();

    const int tx16 = tid & 15, ty16 = tid >> 4;
    const int d0 = ty16 * 8, e0 = tx16 * 8;
    float acc3[8][8];
#pragma unroll
    for (int i = 0; i < 8; i++)
#pragma unroll
        for (int j = 0; j < 8; j++) acc3[i][j] = 0.f;
#pragma unroll 4
    for (int k = 0; k < 64; ++k) {
        float a[8], c[8];
        *(float4*)(a)     = *(const float4*)&buf1[k * 128 + d0];
        *(float4*)(a + 4) = *(const float4*)&buf1[k * 128 + d0 + 4];
        *(float4*)(c)     = *(const float4*)&buf0[k * 128 + e0];
        *(float4*)(c + 4) = *(const float4*)&buf0[k * 128 + e0 + 4];
#pragma unroll
        for (int i = 0; i < 8; i++)
#pragma unroll
            for (int j = 0; j < 8; j++) acc3[i][j] += a[i] * c[j];
    }
    float* Mp = g_Mpart + (size_t)(h * BB + b) * DD * DD;
#pragma unroll
    for (int i = 0; i < 8; i++) {
        *(float4*)&Mp[(d0 + i) * DD + e0] =
            make_float4(acc3[i][0], acc3[i][1], acc3[i][2], acc3[i][3]);
        *(float4*)&Mp[(d0 + i) * DD + e0 + 4] =
            make_float4(acc3[i][4], acc3[i][5], acc3[i][6], acc3[i][7]);
    }
}

// ==========================================================================
// Kernel 4: sum Mparts, convert to bf16 hi/lo transposed [b][e][d]
__global__ __launch_bounds__(256) void mconv() {
    extern __shared__ __align__(128) char smraw[];
    __nv_bfloat16* sh = (__nv_bfloat16*)smraw;   // [e][d]
    __nv_bfloat16* sl = sh + 128 * 132;
    const int b = blockIdx.x, tid = threadIdx.x;

    for (int i = tid; i < 4096; i += 256) {
        int d = i >> 5, p = i & 31;
        float4 s = make_float4(0.f, 0.f, 0.f, 0.f);
#pragma unroll
        for (int h = 0; h < HH; h++) {
            float4 v = ((const float4*)(g_Mpart + (size_t)(h * BB + b) * DD * DD))[i];
            s.x += v.x; s.y += v.y; s.z += v.z; s.w += v.w;
        }
        float vv[4] = {s.x, s.y, s.z, s.w};
#pragma unroll
        for (int j = 0; j < 4; j++) {
            __nv_bfloat16 hb = __float2bfloat16(vv[j]);
            sh[(p * 4 + j) * 132 + d] = hb;
            sl[(p * 4 + j) * 132 + d] =
                __float2bfloat16(vv[j] - __bfloat162float(hb));
        }
    }
    __syncthreads();
    for (int i = tid; i < 4096; i += 256) {
        int e = i >> 5, c = i & 31;
        __nv_bfloat16 th[4], tl[4];
#pragma unroll
        for (int j = 0; j < 4; j++) {
            th[j] = sh[e * 132 + c * 4 + j];
            tl[j] = sl[e * 132 + c * 4 + j];
        }
        size_t gi = ((size_t)b * DD + e) * DD + c * 4;
        *(uint2*)(g_MT_hi + gi) = *(uint2*)th;
        *(uint2*)(g_MT_lo + gi) = *(uint2*)tl;
    }
}

// ==========================================================================
// Kernel 5: out = x @ M via mma.sync.  grid (16, 32), 256 threads.
// smem tiles: A hi/lo [128 n][128 d], B hi/lo [128 e][128 d], row stride 136.
#define SDT 136
#define OTILE_B (128 * SDT * 2)          // 34816
#define OUT_SMEM_BYTES (4 * OTILE_B)     // 139264
__global__ __launch_bounds__(256, 1) void out_mma(float* __restrict__ out) {
    extern __shared__ __align__(128) char sm[];
    uint32_t sb = smem_u32(sm);
    const int b = blockIdx.y, nblk = blockIdx.x * 128;
    const int tid = threadIdx.x, lane = tid & 31, wid = tid >> 5;
    const int m0 = (wid & 1) * 64, n0 = (wid >> 1) * 32;

    const __nv_bfloat16* srcs[4] = {
        g_xnd_hi + ((size_t)b * NN + nblk) * DD,
        g_xnd_lo + ((size_t)b * NN + nblk) * DD,
        g_MT_hi + (size_t)b * DD * DD,
        g_MT_lo + (size_t)b * DD * DD
    };
#pragma unroll
    for (int tile = 0; tile < 4; tile++) {
        const __nv_bfloat16* gb = srcs[tile];
        uint32_t tb = sb + tile * OTILE_B;
        for (int i = tid; i < 2048; i += 256) {
            int row = i >> 4, seg = i & 15;
            CP_ASYNC16(tb + row * 272 + seg * 16, gb + row * 128 + seg * 8);
        }
    }
    CP_ASYNC_COMMIT();
    CP_ASYNC_WAIT0();
    __syncthreads();

    const uint32_t tAh = sb, tAl = sb + OTILE_B;
    const uint32_t tBh = sb + 2 * OTILE_B, tBl = sb + 3 * OTILE_B;

    float acc[4][4][4];
#pragma unroll
    for (int mi = 0; mi < 4; mi++)
#pragma unroll
        for (int nj = 0; nj < 4; nj++)
#pragma unroll
            for (int q = 0; q < 4; q++) acc[mi][nj][q] = 0.f;

#pragma unroll
    for (int ko = 0; ko < 128; ko += 16) {
        uint32_t Ah[4][4], Al[4][4], Bh[2][4], Bl[2][4];
        const int arow = lane & 15;
        const int acolB = (ko + (lane >> 4) * 8) * 2;
#pragma unroll
        for (int mi = 0; mi < 4; mi++) {
            uint32_t o = (m0 + mi * 16 + arow) * 272 + acolB;
            ldsm4(Ah[mi], tAh + o);
            ldsm4(Al[mi], tAl + o);
        }
#pragma unroll
        for (int njp = 0; njp < 2; njp++) {
            uint32_t o = (n0 + njp * 16 + arow) * 272 + acolB;
            ldsm4(Bh[njp], tBh + o);
            ldsm4(Bl[njp], tBl + o);
        }
#pragma unroll
        for (int mi = 0; mi < 4; mi++)
#pragma unroll
            for (int nj = 0; nj < 4; nj++) {
                int njp = nj >> 1, odd = nj & 1;
                uint32_t bh0 = Bh[njp][odd], bh1 = Bh[njp][odd + 2];
                uint32_t bl0 = Bl[njp][odd], bl1 = Bl[njp][odd + 2];
                mma_bf16(acc[mi][nj], Ah[mi], bh0, bh1);
                mma_bf16(acc[mi][nj], Ah[mi], bl0, bl1);
                mma_bf16(acc[mi][nj], Al[mi], bh0, bh1);
            }
    }

    float* ob = out + ((size_t)b * NN + nblk) * DD;
    const int g = lane >> 2, t = lane & 3;
#pragma unroll
    for (int mi = 0; mi < 4; mi++)
#pragma unroll
        for (int nj = 0; nj < 4; nj++) {
            int r = m0 + mi * 16 + g, cc = n0 + nj * 8 + t * 2;
            *(float2*)&ob[r * DD + cc] =
                make_float2(acc[mi][nj][0], acc[mi][nj][1]);
            *(float2*)&ob[(r + 8) * DD + cc] =
                make_float2(acc[mi][nj][2], acc[mi][nj][3]);
        }
}

// ==========================================================================
extern "C" void kernel_launch(void* const* d_in, const int* in_sizes, int n_in,
                              void* d_out, int out_size) {
    const float* x  = (const float*)d_in[0];  // [32, 2048, 128]
    const float* Wk = (const float*)d_in[1];  // [8, 64, 128]
    const float* Wq = (const float*)d_in[2];  // [8, 64, 128]
    const float* Wv = (const float*)d_in[3];  // [8, 128, 128]
    float* out = (float*)d_out;               // [32, 2048, 128]

    cudaFuncSetAttribute(convert_x, cudaFuncAttributeMaxDynamicSharedMemorySize,
                         CONV_SMEM_BYTES);
    cudaFuncSetAttribute(mconv, cudaFuncAttributeMaxDynamicSharedMemorySize,
                         CONV_SMEM_BYTES);
    cudaFuncSetAttribute(gram_mma, cudaFuncAttributeMaxDynamicSharedMemorySize,
                         GRAM_SMEM_BYTES);
    cudaFuncSetAttribute(out_mma, cudaFuncAttributeMaxDynamicSharedMemorySize,
                         OUT_SMEM_BYTES);
    cudaFuncSetAttribute(mid_kernel, cudaFuncAttributeMaxDynamicSharedMemorySize,
                         MID_SMEM_BYTES);

    convert_x<<<dim3(16, 32), 256, CONV_SMEM_BYTES>>>(x);
    gram_mma<<<dim3(NSPLIT, 32), 256, GRAM_SMEM_BYTES>>>();
    mid_kernel<<<dim3(8, 32), 256, MID_SMEM_BYTES>>>(Wk, Wq, Wv);
    mconv<<<32, 256, CONV_SMEM_BYTES>>>();
    out_mma<<<dim3(16, 32), 256, OUT_SMEM_BYTES>>>(out);
}

// round 4
// speedup vs baseline: 1.8426x; 1.2893x over previous
#include <cuda_runtime.h>
#include <cuda_bf16.h>
#include <cstdint>

// Problem constants
#define BB 32
#define NN 2048
#define DD 128
#define HH 8
#define KQ 64
#define NSPLIT 4

// ------------------------------------------------------------------ scratch
__device__ float g_Spart[NSPLIT * BB * DD * DD];    // gram partials per split
__device__ float g_Mpart[HH * BB * DD * DD];        // M partials per head
__device__ __nv_bfloat16 g_xnd_hi[BB * NN * DD];    // x hi, [b][n][d]
__device__ __nv_bfloat16 g_xnd_lo[BB * NN * DD];
__device__ __nv_bfloat16 g_Md_hi[BB * DD * DD];     // M hi, [b][d][e]
__device__ __nv_bfloat16 g_Md_lo[BB * DD * DD];

// ------------------------------------------------------------------ helpers
__device__ __forceinline__ uint32_t smem_u32(const void* p) {
    uint32_t a;
    asm("{ .reg .u64 t; cvta.to.shared.u64 t, %1; cvt.u32.u64 %0, t; }"
        : "=r"(a) : "l"(p));
    return a;
}

#define CP_ASYNC16(saddr, gptr) \
    asm volatile("cp.async.cg.shared.global [%0], [%1], 16;" \
                 :: "r"(saddr), "l"(gptr) : "memory")
#define CP_ASYNC_COMMIT() asm volatile("cp.async.commit_group;" ::: "memory")
#define CP_ASYNC_WAIT0()  asm volatile("cp.async.wait_group 0;" ::: "memory")
#define CP_ASYNC_WAIT1()  asm volatile("cp.async.wait_group 1;" ::: "memory")

__device__ __forceinline__ void ldsm4(uint32_t* r, uint32_t addr) {
    asm volatile("ldmatrix.sync.aligned.m8n8.x4.shared.b16 {%0,%1,%2,%3}, [%4];"
                 : "=r"(r[0]), "=r"(r[1]), "=r"(r[2]), "=r"(r[3]) : "r"(addr));
}
__device__ __forceinline__ void ldsm4t(uint32_t* r, uint32_t addr) {
    asm volatile("ldmatrix.sync.aligned.m8n8.x4.trans.shared.b16 {%0,%1,%2,%3}, [%4];"
                 : "=r"(r[0]), "=r"(r[1]), "=r"(r[2]), "=r"(r[3]) : "r"(addr));
}

__device__ __forceinline__ void mma_bf16(float* d, const uint32_t* a,
                                         uint32_t b0, uint32_t b1) {
    asm volatile(
        "mma.sync.aligned.m16n8k16.row.col.f32.bf16.bf16.f32 "
        "{%0,%1,%2,%3}, {%4,%5,%6,%7}, {%8,%9}, {%0,%1,%2,%3};"
        : "+f"(d[0]), "+f"(d[1]), "+f"(d[2]), "+f"(d[3])
        : "r"(a[0]), "r"(a[1]), "r"(a[2]), "r"(a[3]), "r"(b0), "r"(b1));
}

// ==========================================================================
// Kernel 1: x fp32 -> hi/lo bf16, [b][n][d] layout (pure streaming)
__global__ __launch_bounds__(256) void convert_x(const float* __restrict__ x) {
    size_t idx = (size_t)blockIdx.x * blockDim.x + threadIdx.x;  // 2097152 f4
    float4 v = ((const float4*)x)[idx];
    float vv[4] = {v.x, v.y, v.z, v.w};
    __nv_bfloat16 h[4], l[4];
#pragma unroll
    for (int j = 0; j < 4; j++) {
        h[j] = __float2bfloat16(vv[j]);
        l[j] = __float2bfloat16(vv[j] - __bfloat162float(h[j]));
    }
    *(uint2*)(g_xnd_hi + idx * 4) = *(uint2*)h;
    *(uint2*)(g_xnd_lo + idx * 4) = *(uint2*)l;
}

// ==========================================================================
// Kernel 2: Gram partials via mma.sync, trans-ldmatrix operands.
// grid (NSPLIT, 32), 256 threads.  CTA: Spart = x[nrange]^T x[nrange], K=512.
// smem: 2 stages x (hi,lo) tiles of [64 n][128 d] bf16, row stride 272 B.
#define GSTR 272
#define GTILE_B (64 * GSTR)              // 17408
#define GRAM_SMEM_BYTES (4 * GTILE_B)    // 69632
__global__ __launch_bounds__(256, 1) void gram_mma() {
    extern __shared__ __align__(128) char sm[];
    uint32_t sb = smem_u32(sm);
    const int b = blockIdx.y, split = blockIdx.x;
    const int nbase = split * 512;
    const int tid = threadIdx.x, lane = tid & 31, wid = tid >> 5;
    const int m0 = (wid & 1) * 64, n0 = (wid >> 1) * 32;

    const __nv_bfloat16* gh = g_xnd_hi + (size_t)b * NN * DD;
    const __nv_bfloat16* gl = g_xnd_lo + (size_t)b * NN * DD;

    float acc[4][4][4];
#pragma unroll
    for (int mi = 0; mi < 4; mi++)
#pragma unroll
        for (int nj = 0; nj < 4; nj++)
#pragma unroll
            for (int q = 0; q < 4; q++) acc[mi][nj][q] = 0.f;

    // trans-ldmatrix lane geometry (shared by A and B fragments)
    const int kr = (lane & 7) + ((lane >> 4) << 3);       // k row 0..15
    const int cshift = ((lane >> 3) & 1) << 3;            // +0 / +8 col

#define GRAM_ISSUE(c)                                                          \
    do {                                                                       \
        int st_ = (c) & 1;                                                     \
        int nc_ = nbase + (c) * 64;                                            \
        uint32_t th_ = sb + (st_ * 2) * GTILE_B;                               \
        uint32_t tl_ = th_ + GTILE_B;                                          \
        for (int i = tid; i < 1024; i += 256) {                                \
            int row = i >> 4, seg = i & 15;                                    \
            uint32_t off = row * GSTR + seg * 16;                              \
            const __nv_bfloat16* gp = gh + (size_t)(nc_ + row) * DD + seg * 8; \
            const __nv_bfloat16* lp = gl + (size_t)(nc_ + row) * DD + seg * 8; \
            CP_ASYNC16(th_ + off, gp);                                         \
            CP_ASYNC16(tl_ + off, lp);                                         \
        }                                                                      \
        CP_ASYNC_COMMIT();                                                     \
    } while (0)

    GRAM_ISSUE(0);
    for (int c = 0; c < 8; c++) {
        if (c + 1 < 8) { GRAM_ISSUE(c + 1); CP_ASYNC_WAIT1(); }
        else           { CP_ASYNC_WAIT0(); }
        __syncthreads();
        uint32_t th = sb + ((c & 1) * 2) * GTILE_B;
        uint32_t tl = th + GTILE_B;
#pragma unroll
        for (int ko = 0; ko < 64; ko += 16) {
            uint32_t Ah[4][4], Al[4][4], Bh[2][4], Bl[2][4];
            const uint32_t rowoff = (ko + kr) * GSTR;
#pragma unroll
            for (int mi = 0; mi < 4; mi++) {
                uint32_t o = rowoff + (m0 + mi * 16 + cshift) * 2;
                ldsm4t(Ah[mi], th + o);
                ldsm4t(Al[mi], tl + o);
            }
#pragma unroll
            for (int njp = 0; njp < 2; njp++) {
                uint32_t o = rowoff + (n0 + njp * 16 + cshift) * 2;
                ldsm4t(Bh[njp], th + o);
                ldsm4t(Bl[njp], tl + o);
            }
#pragma unroll
            for (int mi = 0; mi < 4; mi++)
#pragma unroll
                for (int nj = 0; nj < 4; nj++) {
                    int njp = nj >> 1, odd = nj & 1;
                    uint32_t bh0 = Bh[njp][odd], bh1 = Bh[njp][odd + 2];
                    uint32_t bl0 = Bl[njp][odd], bl1 = Bl[njp][odd + 2];
                    mma_bf16(acc[mi][nj], Ah[mi], bh0, bh1);
                    mma_bf16(acc[mi][nj], Ah[mi], bl0, bl1);
                    mma_bf16(acc[mi][nj], Al[mi], bh0, bh1);
                }
        }
        __syncthreads();
    }

    float* Sp = g_Spart + (size_t)(split * BB + b) * (DD * DD);
    const int g = lane >> 2, t = lane & 3;
#pragma unroll
    for (int mi = 0; mi < 4; mi++)
#pragma unroll
        for (int nj = 0; nj < 4; nj++) {
            int r = m0 + mi * 16 + g, cc = n0 + nj * 8 + t * 2;
            *(float2*)&Sp[r * DD + cc] =
                make_float2(acc[mi][nj][0], acc[mi][nj][1]);
            *(float2*)&Sp[(r + 8) * DD + cc] =
                make_float2(acc[mi][nj][2], acc[mi][nj][3]);
        }
}

// ==========================================================================
// Kernel 3: per (b,h): Mpart[h][b] = Wq_h^T (Wk_h (sum_p Spart)) Wv_h^T
#define ST_KT 68
#define ST_VT 132
#define BUF0_F (128 * ST_KT)
#define BUF1_F (128 * ST_VT)
#define MID_SMEM_BYTES ((BUF0_F + BUF1_F) * 4)

__global__ __launch_bounds__(256) void mid_kernel(const float* __restrict__ Wk,
                                                  const float* __restrict__ Wq,
                                                  const float* __restrict__ Wv) {
    extern __shared__ float smem[];
    float* buf0 = smem;
    float* buf1 = smem + BUF0_F;
    const int h = blockIdx.x, b = blockIdx.y;
    const int tid = threadIdx.x;

    const float* Wkh = Wk + h * KQ * DD;
    for (int idx = tid; idx < KQ * DD; idx += 256) {
        int k = idx >> 7, d = idx & 127;
        buf0[d * ST_KT + k] = Wkh[idx];
    }
    for (int i = tid; i < DD * DD / 4; i += 256) {
        float4 s = make_float4(0.f, 0.f, 0.f, 0.f);
#pragma unroll
        for (int p = 0; p < NSPLIT; p++) {
            float4 v = ((const float4*)(g_Spart + (size_t)(p * BB + b) * DD * DD))[i];
            s.x += v.x; s.y += v.y; s.z += v.z; s.w += v.w;
        }
        ((float4*)buf1)[i] = s;
    }
    __syncthreads();

    const int ty = tid >> 5, tx = tid & 31;
    const int r0 = ty * 8, c0 = tx * 4;

    float acc1[8][4];
#pragma unroll
    for (int i = 0; i < 8; i++)
#pragma unroll
        for (int j = 0; j < 4; j++) acc1[i][j] = 0.f;
#pragma unroll 4
    for (int d = 0; d < 128; ++d) {
        float a[8], c[4];
        *(float4*)(a)     = *(const float4*)&buf0[d * ST_KT + r0];
        *(float4*)(a + 4) = *(const float4*)&buf0[d * ST_KT + r0 + 4];
        *(float4*)(c)     = *(const float4*)&buf1[d * 128 + c0];
#pragma unroll
        for (int i = 0; i < 8; i++)
#pragma unroll
            for (int j = 0; j < 4; j++) acc1[i][j] += a[i] * c[j];
    }
    __syncthreads();

#pragma unroll
    for (int j = 0; j < 4; j++) {
        *(float4*)&buf0[(c0 + j) * ST_KT + r0] =
            make_float4(acc1[0][j], acc1[1][j], acc1[2][j], acc1[3][j]);
        *(float4*)&buf0[(c0 + j) * ST_KT + r0 + 4] =
            make_float4(acc1[4][j], acc1[5][j], acc1[6][j], acc1[7][j]);
    }
    const float* Wvh = Wv + h * DD * DD;
    for (int idx = tid; idx < DD * DD; idx += 256) {
        int e = idx >> 7, d = idx & 127;
        buf1[d * ST_VT + e] = Wvh[idx];
    }
    __syncthreads();

    float acc2[8][4];
#pragma unroll
    for (int i = 0; i < 8; i++)
#pragma unroll
        for (int j = 0; j < 4; j++) acc2[i][j] = 0.f;
#pragma unroll 4
    for (int d = 0; d < 128; ++d) {
        float a[8], c[4];
        *(float4*)(a)     = *(const float4*)&buf0[d * ST_KT + r0];
        *(float4*)(a + 4) = *(const float4*)&buf0[d * ST_KT + r0 + 4];
        *(float4*)(c)     = *(const float4*)&buf1[d * ST_VT + c0];
#pragma unroll
        for (int i = 0; i < 8; i++)
#pragma unroll
            for (int j = 0; j < 4; j++) acc2[i][j] += a[i] * c[j];
    }
    __syncthreads();

#pragma unroll
    for (int i = 0; i < 8; i++)
        *(float4*)&buf0[(r0 + i) * 128 + c0] =
            make_float4(acc2[i][0], acc2[i][1], acc2[i][2], acc2[i][3]);
    const float* Wqh = Wq + h * KQ * DD;
    for (int i = tid; i < KQ * DD / 4; i += 256)
        ((float4*)buf1)[i] = ((const float4*)Wqh)[i];
    __syncthreads();

    const int tx16 = tid & 15, ty16 = tid >> 4;
    const int d0 = ty16 * 8, e0 = tx16 * 8;
    float acc3[8][8];
#pragma unroll
    for (int i = 0; i < 8; i++)
#pragma unroll
        for (int j = 0; j < 8; j++) acc3[i][j] = 0.f;
#pragma unroll 4
    for (int k = 0; k < 64; ++k) {
        float a[8], c[8];
        *(float4*)(a)     = *(const float4*)&buf1[k * 128 + d0];
        *(float4*)(a + 4) = *(const float4*)&buf1[k * 128 + d0 + 4];
        *(float4*)(c)     = *(const float4*)&buf0[k * 128 + e0];
        *(float4*)(c + 4) = *(const float4*)&buf0[k * 128 + e0 + 4];
#pragma unroll
        for (int i = 0; i < 8; i++)
#pragma unroll
            for (int j = 0; j < 8; j++) acc3[i][j] += a[i] * c[j];
    }
    float* Mp = g_Mpart + (size_t)(h * BB + b) * DD * DD;
#pragma unroll
    for (int i = 0; i < 8; i++) {
        *(float4*)&Mp[(d0 + i) * DD + e0] =
            make_float4(acc3[i][0], acc3[i][1], acc3[i][2], acc3[i][3]);
        *(float4*)&Mp[(d0 + i) * DD + e0 + 4] =
            make_float4(acc3[i][4], acc3[i][5], acc3[i][6], acc3[i][7]);
    }
}

// ==========================================================================
// Kernel 4: sum Mparts over heads, convert to bf16 hi/lo, KEEP [b][d][e].
// grid (8, 32): CTA handles 16 d-rows of one b.
__global__ __launch_bounds__(256) void mconv() {
    const int b = blockIdx.y, ds = blockIdx.x;
    const int tid = threadIdx.x;
    const size_t base = (size_t)b * DD * DD + ds * 16 * DD;  // in floats

    for (int i = tid; i < 512; i += 256) {          // 512 float4 = 16x128
        float4 s = make_float4(0.f, 0.f, 0.f, 0.f);
#pragma unroll
        for (int h = 0; h < HH; h++) {
            float4 v = *(const float4*)(g_Mpart + (size_t)h * BB * DD * DD +
                                        base + i * 4);
            s.x += v.x; s.y += v.y; s.z += v.z; s.w += v.w;
        }
        float vv[4] = {s.x, s.y, s.z, s.w};
        __nv_bfloat16 hh[4], ll[4];
#pragma unroll
        for (int j = 0; j < 4; j++) {
            hh[j] = __float2bfloat16(vv[j]);
            ll[j] = __float2bfloat16(vv[j] - __bfloat162float(hh[j]));
        }
        *(uint2*)(g_Md_hi + base + i * 4) = *(uint2*)hh;
        *(uint2*)(g_Md_lo + base + i * 4) = *(uint2*)ll;
    }
}

// ==========================================================================
// Kernel 5: out = x @ M via mma.sync.  grid (16, 32), 256 threads.
// A hi/lo: [128 n][128 d] (non-trans).  B hi/lo: [128 d][128 e] (trans ldsm).
#define OSTR 272
#define OTILE_B (128 * OSTR)             // 34816
#define OUT_SMEM_BYTES (4 * OTILE_B)     // 139264
__global__ __launch_bounds__(256, 1) void out_mma(float* __restrict__ out) {
    extern __shared__ __align__(128) char sm[];
    uint32_t sb = smem_u32(sm);
    const int b = blockIdx.y, nblk = blockIdx.x * 128;
    const int tid = threadIdx.x, lane = tid & 31, wid = tid >> 5;
    const int m0 = (wid & 1) * 64, n0 = (wid >> 1) * 32;

    const __nv_bfloat16* srcs[4] = {
        g_xnd_hi + ((size_t)b * NN + nblk) * DD,   // A hi [n][d]
        g_xnd_lo + ((size_t)b * NN + nblk) * DD,   // A lo
        g_Md_hi + (size_t)b * DD * DD,             // B hi [d][e]
        g_Md_lo + (size_t)b * DD * DD              // B lo
    };
#pragma unroll
    for (int tile = 0; tile < 4; tile++) {
        const __nv_bfloat16* gb = srcs[tile];
        uint32_t tb = sb + tile * OTILE_B;
        for (int i = tid; i < 2048; i += 256) {
            int row = i >> 4, seg = i & 15;
            CP_ASYNC16(tb + row * OSTR + seg * 16, gb + row * 128 + seg * 8);
        }
    }
    CP_ASYNC_COMMIT();
    CP_ASYNC_WAIT0();
    __syncthreads();

    const uint32_t tAh = sb, tAl = sb + OTILE_B;
    const uint32_t tBh = sb + 2 * OTILE_B, tBl = sb + 3 * OTILE_B;

    float acc[4][4][4];
#pragma unroll
    for (int mi = 0; mi < 4; mi++)
#pragma unroll
        for (int nj = 0; nj < 4; nj++)
#pragma unroll
            for (int q = 0; q < 4; q++) acc[mi][nj][q] = 0.f;

    const int arow = lane & 15;
    const int kr = (lane & 7) + ((lane >> 4) << 3);
    const int cshift = ((lane >> 3) & 1) << 3;

#pragma unroll
    for (int ko = 0; ko < 128; ko += 16) {
        uint32_t Ah[4][4], Al[4][4], Bh[2][4], Bl[2][4];
        const int acolB = (ko + (lane >> 4) * 8) * 2;
#pragma unroll
        for (int mi = 0; mi < 4; mi++) {
            uint32_t o = (m0 + mi * 16 + arow) * OSTR + acolB;
            ldsm4(Ah[mi], tAh + o);
            ldsm4(Al[mi], tAl + o);
        }
        const uint32_t browoff = (ko + kr) * OSTR;
#pragma unroll
        for (int njp = 0; njp < 2; njp++) {
            uint32_t o = browoff + (n0 + njp * 16 + cshift) * 2;
            ldsm4t(Bh[njp], tBh + o);
            ldsm4t(Bl[njp], tBl + o);
        }
#pragma unroll
        for (int mi = 0; mi < 4; mi++)
#pragma unroll
            for (int nj = 0; nj < 4; nj++) {
                int njp = nj >> 1, odd = nj & 1;
                uint32_t bh0 = Bh[njp][odd], bh1 = Bh[njp][odd + 2];
                uint32_t bl0 = Bl[njp][odd], bl1 = Bl[njp][odd + 2];
                mma_bf16(acc[mi][nj], Ah[mi], bh0, bh1);
                mma_bf16(acc[mi][nj], Ah[mi], bl0, bl1);
                mma_bf16(acc[mi][nj], Al[mi], bh0, bh1);
            }
    }

    float* ob = out + ((size_t)b * NN + nblk) * DD;
    const int g = lane >> 2, t = lane & 3;
#pragma unroll
    for (int mi = 0; mi < 4; mi++)
#pragma unroll
        for (int nj = 0; nj < 4; nj++) {
            int r = m0 + mi * 16 + g, cc = n0 + nj * 8 + t * 2;
            *(float2*)&ob[r * DD + cc] =
                make_float2(acc[mi][nj][0], acc[mi][nj][1]);
            *(float2*)&ob[(r + 8) * DD + cc] =
                make_float2(acc[mi][nj][2], acc[mi][nj][3]);
        }
}

// ==========================================================================
extern "C" void kernel_launch(void* const* d_in, const int* in_sizes, int n_in,
                              void* d_out, int out_size) {
    const float* x  = (const float*)d_in[0];  // [32, 2048, 128]
    const float* Wk = (const float*)d_in[1];  // [8, 64, 128]
    const float* Wq = (const float*)d_in[2];  // [8, 64, 128]
    const float* Wv = (const float*)d_in[3];  // [8, 128, 128]
    float* out = (float*)d_out;               // [32, 2048, 128]

    cudaFuncSetAttribute(gram_mma, cudaFuncAttributeMaxDynamicSharedMemorySize,
                         GRAM_SMEM_BYTES);
    cudaFuncSetAttribute(out_mma, cudaFuncAttributeMaxDynamicSharedMemorySize,
                         OUT_SMEM_BYTES);
    cudaFuncSetAttribute(mid_kernel, cudaFuncAttributeMaxDynamicSharedMemorySize,
                         MID_SMEM_BYTES);

    convert_x<<<8192, 256>>>(x);
    gram_mma<<<dim3(NSPLIT, 32), 256, GRAM_SMEM_BYTES>>>();
    mid_kernel<<<dim3(8, 32), 256, MID_SMEM_BYTES>>>(Wk, Wq, Wv);
    mconv<<<dim3(8, 32), 256>>>();
    out_mma<<<dim3(16, 32), 256, OUT_SMEM_BYTES>>>(out);
}

// round 5
// speedup vs baseline: 2.2880x; 1.2417x over previous
#include <cuda_runtime.h>
#include <cuda_bf16.h>
#include <cstdint>

// Problem constants
#define BB 32
#define NN 2048
#define DD 128
#define HH 8
#define KQ 64
#define NSPLIT 4

// ------------------------------------------------------------------ scratch
__device__ float g_Spart[NSPLIT * BB * DD * DD];     // gram partials (fp32)
__device__ float g_Mpart[HH * BB * DD * DD];         // M partials per head
__device__ __nv_bfloat16 g_S_hi[BB * DD * DD];       // S hi/lo, [b][d][d']
__device__ __nv_bfloat16 g_S_lo[BB * DD * DD];
__device__ __nv_bfloat16 g_Md_hi[BB * DD * DD];      // M hi/lo, [b][d][e]
__device__ __nv_bfloat16 g_Md_lo[BB * DD * DD];
__device__ __nv_bfloat16 g_Wk_hi[HH * KQ * DD];
__device__ __nv_bfloat16 g_Wk_lo[HH * KQ * DD];
__device__ __nv_bfloat16 g_Wq_hi[HH * KQ * DD];
__device__ __nv_bfloat16 g_Wq_lo[HH * KQ * DD];
__device__ __nv_bfloat16 g_Wv_hi[HH * DD * DD];
__device__ __nv_bfloat16 g_Wv_lo[HH * DD * DD];

// ------------------------------------------------------------------ helpers
__device__ __forceinline__ uint32_t smem_u32(const void* p) {
    uint32_t a;
    asm("{ .reg .u64 t; cvta.to.shared.u64 t, %1; cvt.u32.u64 %0, t; }"
        : "=r"(a) : "l"(p));
    return a;
}

#define CP_ASYNC16(saddr, gptr) \
    asm volatile("cp.async.cg.shared.global [%0], [%1], 16;" \
                 :: "r"(saddr), "l"(gptr) : "memory")
#define CP_ASYNC_COMMIT() asm volatile("cp.async.commit_group;" ::: "memory")
#define CP_ASYNC_WAIT0()  asm volatile("cp.async.wait_group 0;" ::: "memory")
#define CP_ASYNC_WAIT1()  asm volatile("cp.async.wait_group 1;" ::: "memory")

__device__ __forceinline__ void ldsm4(uint32_t* r, uint32_t addr) {
    asm volatile("ldmatrix.sync.aligned.m8n8.x4.shared.b16 {%0,%1,%2,%3}, [%4];"
                 : "=r"(r[0]), "=r"(r[1]), "=r"(r[2]), "=r"(r[3]) : "r"(addr));
}
__device__ __forceinline__ void ldsm4t(uint32_t* r, uint32_t addr) {
    asm volatile("ldmatrix.sync.aligned.m8n8.x4.trans.shared.b16 {%0,%1,%2,%3}, [%4];"
                 : "=r"(r[0]), "=r"(r[1]), "=r"(r[2]), "=r"(r[3]) : "r"(addr));
}

__device__ __forceinline__ void mma_bf16(float* d, const uint32_t* a,
                                         uint32_t b0, uint32_t b1) {
    asm volatile(
        "mma.sync.aligned.m16n8k16.row.col.f32.bf16.bf16.f32 "
        "{%0,%1,%2,%3}, {%4,%5,%6,%7}, {%8,%9}, {%0,%1,%2,%3};"
        : "+f"(d[0]), "+f"(d[1]), "+f"(d[2]), "+f"(d[3])
        : "r"(a[0]), "r"(a[1]), "r"(a[2]), "r"(a[3]), "r"(b0), "r"(b1));
}

__device__ __forceinline__ void packpair(float v0, float v1,
                                         uint32_t& hi, uint32_t& lo) {
    __nv_bfloat16 h0 = __float2bfloat16(v0);
    __nv_bfloat16 h1 = __float2bfloat16(v1);
    __nv_bfloat16 l0 = __float2bfloat16(v0 - __bfloat162float(h0));
    __nv_bfloat16 l1 = __float2bfloat16(v1 - __bfloat162float(h1));
    hi = (uint32_t)*(uint16_t*)&h0 | ((uint32_t)*(uint16_t*)&h1 << 16);
    lo = (uint32_t)*(uint16_t*)&l0 | ((uint32_t)*(uint16_t*)&l1 << 16);
}

// ==========================================================================
// Kernel W: convert Wk, Wq, Wv to hi/lo bf16 (65536 float4 total)
__global__ __launch_bounds__(256) void wconv(const float* __restrict__ Wk,
                                             const float* __restrict__ Wq,
                                             const float* __restrict__ Wv) {
    int i4 = blockIdx.x * 256 + threadIdx.x;   // 0..65535
    const float* src;
    __nv_bfloat16 *dh, *dl;
    int off;
    if (i4 < 16384)      { src = Wk; dh = g_Wk_hi; dl = g_Wk_lo; off = i4; }
    else if (i4 < 32768) { src = Wq; dh = g_Wq_hi; dl = g_Wq_lo; off = i4 - 16384; }
    else                 { src = Wv; dh = g_Wv_hi; dl = g_Wv_lo; off = i4 - 32768; }
    float4 v = ((const float4*)src)[off];
    float vv[4] = {v.x, v.y, v.z, v.w};
    __nv_bfloat16 h[4], l[4];
#pragma unroll
    for (int j = 0; j < 4; j++) {
        h[j] = __float2bfloat16(vv[j]);
        l[j] = __float2bfloat16(vv[j] - __bfloat162float(h[j]));
    }
    *(uint2*)(dh + (size_t)off * 4) = *(uint2*)h;
    *(uint2*)(dl + (size_t)off * 4) = *(uint2*)l;
}

// ==========================================================================
// Kernel G: Gram partials, fp32 x read + inline hi/lo conversion.
// grid (NSPLIT, 32), 256 threads.  K=512 per CTA, 8 chunks of 64 n-rows.
// smem: fp32 staging 2x[64][544B] + bf16 tiles 2 stages x hi/lo [64][272B]
#define GSTR 272
#define GFST 544
#define G_STAGE(s)   (sb + (s) * 34816u)
#define G_TILE(s, p) (sb + 69632u + (s) * 34816u + (p) * 17408u)
#define GRAM_SMEM_BYTES 139264
__global__ __launch_bounds__(256, 1) void gram_mma(const float* __restrict__ x) {
    extern __shared__ __align__(128) char sm[];
    uint32_t sb = smem_u32(sm);
    const int b = blockIdx.y, split = blockIdx.x;
    const int nbase = split * 512;
    const int tid = threadIdx.x, lane = tid & 31, wid = tid >> 5;
    const int m0 = (wid & 1) * 64, n0 = (wid >> 1) * 32;
    const float* xb = x + (size_t)b * NN * DD;

    float acc[4][4][4];
#pragma unroll
    for (int mi = 0; mi < 4; mi++)
#pragma unroll
        for (int nj = 0; nj < 4; nj++)
#pragma unroll
            for (int q = 0; q < 4; q++) acc[mi][nj][q] = 0.f;

    const int kr = (lane & 7) + ((lane >> 4) << 3);
    const int cshift = ((lane >> 3) & 1) << 3;

#define GRAM_ISSUE(c)                                                          \
    do {                                                                       \
        int nc_ = nbase + (c) * 64;                                            \
        uint32_t stg_ = G_STAGE((c) & 1);                                      \
        for (int i = tid; i < 2048; i += 256) {                                \
            int row = i >> 5, seg = i & 31;                                    \
            CP_ASYNC16(stg_ + row * GFST + seg * 16,                           \
                       xb + (size_t)(nc_ + row) * DD + seg * 4);               \
        }                                                                      \
        CP_ASYNC_COMMIT();                                                     \
    } while (0)

    GRAM_ISSUE(0);
    for (int c = 0; c < 8; c++) {
        if (c + 1 < 8) { GRAM_ISSUE(c + 1); CP_ASYNC_WAIT1(); }
        else           { CP_ASYNC_WAIT0(); }
        __syncthreads();
        // convert staged fp32 chunk -> hi/lo bf16 tiles
        {
            const char* stg = sm + (G_STAGE(c & 1) - sb);
            char* th = sm + (G_TILE(c & 1, 0) - sb);
            char* tl = sm + (G_TILE(c & 1, 1) - sb);
            for (int i = tid; i < 2048; i += 256) {
                int row = i >> 5, seg = i & 31;
                float4 v = *(const float4*)(stg + row * GFST + seg * 16);
                uint32_t h0, l0, h1, l1;
                packpair(v.x, v.y, h0, l0);
                packpair(v.z, v.w, h1, l1);
                *(uint2*)(th + row * GSTR + seg * 8) = make_uint2(h0, h1);
                *(uint2*)(tl + row * GSTR + seg * 8) = make_uint2(l0, l1);
            }
        }
        __syncthreads();
        uint32_t th = G_TILE(c & 1, 0), tl = G_TILE(c & 1, 1);
#pragma unroll
        for (int ko = 0; ko < 64; ko += 16) {
            uint32_t Ah[4][4], Al[4][4], Bh[2][4], Bl[2][4];
            const uint32_t rowoff = (ko + kr) * GSTR;
#pragma unroll
            for (int mi = 0; mi < 4; mi++) {
                uint32_t o = rowoff + (m0 + mi * 16 + cshift) * 2;
                ldsm4t(Ah[mi], th + o);
                ldsm4t(Al[mi], tl + o);
            }
#pragma unroll
            for (int njp = 0; njp < 2; njp++) {
                uint32_t o = rowoff + (n0 + njp * 16 + cshift) * 2;
                ldsm4t(Bh[njp], th + o);
                ldsm4t(Bl[njp], tl + o);
            }
#pragma unroll
            for (int mi = 0; mi < 4; mi++)
#pragma unroll
                for (int nj = 0; nj < 4; nj++) {
                    int njp = nj >> 1, odd = nj & 1;
                    uint32_t bh0 = Bh[njp][odd], bh1 = Bh[njp][odd + 2];
                    uint32_t bl0 = Bl[njp][odd], bl1 = Bl[njp][odd + 2];
                    mma_bf16(acc[mi][nj], Ah[mi], bh0, bh1);
                    mma_bf16(acc[mi][nj], Ah[mi], bl0, bl1);
                    mma_bf16(acc[mi][nj], Al[mi], bh0, bh1);
                }
        }
        __syncthreads();
    }

    float* Sp = g_Spart + (size_t)(split * BB + b) * (DD * DD);
    const int g = lane >> 2, t = lane & 3;
#pragma unroll
    for (int mi = 0; mi < 4; mi++)
#pragma unroll
        for (int nj = 0; nj < 4; nj++) {
            int r = m0 + mi * 16 + g, cc = n0 + nj * 8 + t * 2;
            *(float2*)&Sp[r * DD + cc] =
                make_float2(acc[mi][nj][0], acc[mi][nj][1]);
            *(float2*)&Sp[(r + 8) * DD + cc] =
                make_float2(acc[mi][nj][2], acc[mi][nj][3]);
        }
}

// ==========================================================================
// Kernel S: sum Spart -> S hi/lo bf16 [b][d][d'].  grid (4, 32).
__global__ __launch_bounds__(256) void sconv() {
    const int b = blockIdx.y, ds = blockIdx.x;
    const int tid = threadIdx.x;
    const size_t base = (size_t)b * DD * DD + ds * 32 * DD;

    for (int i = tid; i < 1024; i += 256) {     // 1024 float4 = 32x128
        float4 s = make_float4(0.f, 0.f, 0.f, 0.f);
#pragma unroll
        for (int p = 0; p < NSPLIT; p++) {
            float4 v = *(const float4*)(g_Spart + (size_t)p * BB * DD * DD +
                                        base + i * 4);
            s.x += v.x; s.y += v.y; s.z += v.z; s.w += v.w;
        }
        float vv[4] = {s.x, s.y, s.z, s.w};
        __nv_bfloat16 hh[4], ll[4];
#pragma unroll
        for (int j = 0; j < 4; j++) {
            hh[j] = __float2bfloat16(vv[j]);
            ll[j] = __float2bfloat16(vv[j] - __bfloat162float(hh[j]));
        }
        *(uint2*)(g_S_hi + base + i * 4) = *(uint2*)hh;
        *(uint2*)(g_S_lo + base + i * 4) = *(uint2*)ll;
    }
}

// ==========================================================================
// Kernel M: tensor-core mid.  grid (8, 32), 256 threads (8 warps).
// Per (b,h): T1 = Wk_h S_b ; T2 = T1 Wv_h^T ; Mpart = Wq_h^T T2.
// smem (bytes): sWk 0 (hi/lo 2x17408) | sS 34816 (hi/lo 2x34816;
//   after stage1: Wq hi/lo at 34816, T2 hi/lo at 69632) | sWv 104448
//   (hi/lo 2x34816) | sT1 174080 (hi/lo 2x17408).  Total 208896.
#define MID_SMEM_BYTES 208896
__global__ __launch_bounds__(256, 1) void mid_mma() {
    extern __shared__ __align__(128) char sm[];
    uint32_t sb = smem_u32(sm);
    const int h = blockIdx.x, b = blockIdx.y;
    const int tid = threadIdx.x, lane = tid & 31, wid = tid >> 5;

    const uint32_t sWkh = sb,            sWkl = sb + 17408;
    const uint32_t sSh  = sb + 34816,    sSl  = sb + 69632;
    const uint32_t sWqh = sb + 34816,    sWql = sb + 52224;
    const uint32_t sT2h = sb + 69632,    sT2l = sb + 87040;
    const uint32_t sWvh = sb + 104448,   sWvl = sb + 139264;
    const uint32_t sT1h = sb + 174080,   sT1l = sb + 191488;

    // group 0: Wk + S
    {
        const __nv_bfloat16* wkh = g_Wk_hi + (size_t)h * KQ * DD;
        const __nv_bfloat16* wkl = g_Wk_lo + (size_t)h * KQ * DD;
        for (int i = tid; i < 1024; i += 256) {
            int row = i >> 4, seg = i & 15;
            uint32_t o = row * GSTR + seg * 16;
            CP_ASYNC16(sWkh + o, wkh + row * DD + seg * 8);
            CP_ASYNC16(sWkl + o, wkl + row * DD + seg * 8);
        }
        const __nv_bfloat16* ssh = g_S_hi + (size_t)b * DD * DD;
        const __nv_bfloat16* ssl = g_S_lo + (size_t)b * DD * DD;
        for (int i = tid; i < 2048; i += 256) {
            int row = i >> 4, seg = i & 15;
            uint32_t o = row * GSTR + seg * 16;
            CP_ASYNC16(sSh + o, ssh + row * DD + seg * 8);
            CP_ASYNC16(sSl + o, ssl + row * DD + seg * 8);
        }
        CP_ASYNC_COMMIT();
    }
    // group 1: Wv
    {
        const __nv_bfloat16* wvh = g_Wv_hi + (size_t)h * DD * DD;
        const __nv_bfloat16* wvl = g_Wv_lo + (size_t)h * DD * DD;
        for (int i = tid; i < 2048; i += 256) {
            int row = i >> 4, seg = i & 15;
            uint32_t o = row * GSTR + seg * 16;
            CP_ASYNC16(sWvh + o, wvh + row * DD + seg * 8);
            CP_ASYNC16(sWvl + o, wvl + row * DD + seg * 8);
        }
        CP_ASYNC_COMMIT();
    }

    const int kr = (lane & 7) + ((lane >> 4) << 3);
    const int cshift = ((lane >> 3) & 1) << 3;
    const int arow = lane & 15;
    const int g = lane >> 2, t = lane & 3;

    // Stage 1: T1[64,128] = Wk (A, [k][d] non-trans) @ S (B, [d][d'] trans)
    const int m0s = (wid & 3) * 16, n0s = (wid >> 2) * 64;
    float acc1[8][4];
#pragma unroll
    for (int nj = 0; nj < 8; nj++)
#pragma unroll
        for (int q = 0; q < 4; q++) acc1[nj][q] = 0.f;

    CP_ASYNC_WAIT1();
    __syncthreads();
#pragma unroll
    for (int ko = 0; ko < 128; ko += 16) {
        uint32_t Ah[4], Al[4], Bh[4][4], Bl[4][4];
        const int acolB = (ko + (lane >> 4) * 8) * 2;
        {
            uint32_t o = (m0s + arow) * GSTR + acolB;
            ldsm4(Ah, sWkh + o);
            ldsm4(Al, sWkl + o);
        }
        const uint32_t rowoff = (ko + kr) * GSTR;
#pragma unroll
        for (int njp = 0; njp < 4; njp++) {
            uint32_t o = rowoff + (n0s + njp * 16 + cshift) * 2;
            ldsm4t(Bh[njp], sSh + o);
            ldsm4t(Bl[njp], sSl + o);
        }
#pragma unroll
        for (int nj = 0; nj < 8; nj++) {
            int njp = nj >> 1, odd = nj & 1;
            uint32_t bh0 = Bh[njp][odd], bh1 = Bh[njp][odd + 2];
            uint32_t bl0 = Bl[njp][odd], bl1 = Bl[njp][odd + 2];
            mma_bf16(acc1[nj], Ah, bh0, bh1);
            mma_bf16(acc1[nj], Ah, bl0, bl1);
            mma_bf16(acc1[nj], Al, bh0, bh1);
        }
    }
    __syncthreads();   // all warps done reading S (Wq will overwrite)

    // write T1 hi/lo
#pragma unroll
    for (int nj = 0; nj < 8; nj++) {
        uint32_t h0, l0, h1, l1;
        int cc = n0s + nj * 8 + t * 2;
        packpair(acc1[nj][0], acc1[nj][1], h0, l0);
        packpair(acc1[nj][2], acc1[nj][3], h1, l1);
        *(uint32_t*)(sm + (sT1h - sb) + (m0s + g) * GSTR + cc * 2) = h0;
        *(uint32_t*)(sm + (sT1l - sb) + (m0s + g) * GSTR + cc * 2) = l0;
        *(uint32_t*)(sm + (sT1h - sb) + (m0s + g + 8) * GSTR + cc * 2) = h1;
        *(uint32_t*)(sm + (sT1l - sb) + (m0s + g + 8) * GSTR + cc * 2) = l1;
    }
    // group 2: Wq into old-S slot
    {
        const __nv_bfloat16* wqh = g_Wq_hi + (size_t)h * KQ * DD;
        const __nv_bfloat16* wql = g_Wq_lo + (size_t)h * KQ * DD;
        for (int i = tid; i < 1024; i += 256) {
            int row = i >> 4, seg = i & 15;
            uint32_t o = row * GSTR + seg * 16;
            CP_ASYNC16(sWqh + o, wqh + row * DD + seg * 8);
            CP_ASYNC16(sWql + o, wql + row * DD + seg * 8);
        }
        CP_ASYNC_COMMIT();
    }
    CP_ASYNC_WAIT1();   // Wv done (leaves Wq pending)
    __syncthreads();    // T1 visible, Wv visible

    // Stage 2: T2[64,128] = T1 (A, [k][d'] non-trans) @ Wv (B, [e][d'] non-trans)
    float acc2[8][4];
#pragma unroll
    for (int nj = 0; nj < 8; nj++)
#pragma unroll
        for (int q = 0; q < 4; q++) acc2[nj][q] = 0.f;
#pragma unroll
    for (int ko = 0; ko < 128; ko += 16) {
        uint32_t Ah[4], Al[4], Bh[4][4], Bl[4][4];
        const int acolB = (ko + (lane >> 4) * 8) * 2;
        {
            uint32_t o = (m0s + arow) * GSTR + acolB;
            ldsm4(Ah, sT1h + o);
            ldsm4(Al, sT1l + o);
        }
#pragma unroll
        for (int njp = 0; njp < 4; njp++) {
            uint32_t o = (n0s + njp * 16 + arow) * GSTR + acolB;
            ldsm4(Bh[njp], sWvh + o);
            ldsm4(Bl[njp], sWvl + o);
        }
#pragma unroll
        for (int nj = 0; nj < 8; nj++) {
            int njp = nj >> 1, odd = nj & 1;
            uint32_t bh0 = Bh[njp][odd], bh1 = Bh[njp][odd + 2];
            uint32_t bl0 = Bl[njp][odd], bl1 = Bl[njp][odd + 2];
            mma_bf16(acc2[nj], Ah, bh0, bh1);
            mma_bf16(acc2[nj], Ah, bl0, bl1);
            mma_bf16(acc2[nj], Al, bh0, bh1);
        }
    }
    // write T2 hi/lo (region disjoint from anything stage2 reads)
#pragma unroll
    for (int nj = 0; nj < 8; nj++) {
        uint32_t h0, l0, h1, l1;
        int cc = n0s + nj * 8 + t * 2;
        packpair(acc2[nj][0], acc2[nj][1], h0, l0);
        packpair(acc2[nj][2], acc2[nj][3], h1, l1);
        *(uint32_t*)(sm + (sT2h - sb) + (m0s + g) * GSTR + cc * 2) = h0;
        *(uint32_t*)(sm + (sT2l - sb) + (m0s + g) * GSTR + cc * 2) = l0;
        *(uint32_t*)(sm + (sT2h - sb) + (m0s + g + 8) * GSTR + cc * 2) = h1;
        *(uint32_t*)(sm + (sT2l - sb) + (m0s + g + 8) * GSTR + cc * 2) = l1;
    }
    CP_ASYNC_WAIT0();   // Wq done
    __syncthreads();    // T2 + Wq visible

    // Stage 3: Mpart[128,128] = Wq^T (A trans, [k][d]) @ T2 (B trans, [k][e])
    const int m0 = (wid & 1) * 64, n0 = (wid >> 1) * 32;
    float acc3[4][4][4];
#pragma unroll
    for (int mi = 0; mi < 4; mi++)
#pragma unroll
        for (int nj = 0; nj < 4; nj++)
#pragma unroll
            for (int q = 0; q < 4; q++) acc3[mi][nj][q] = 0.f;
#pragma unroll
    for (int ko = 0; ko < 64; ko += 16) {
        uint32_t Ah[4][4], Al[4][4], Bh[2][4], Bl[2][4];
        const uint32_t rowoff = (ko + kr) * GSTR;
#pragma unroll
        for (int mi = 0; mi < 4; mi++) {
            uint32_t o = rowoff + (m0 + mi * 16 + cshift) * 2;
            ldsm4t(Ah[mi], sWqh + o);
            ldsm4t(Al[mi], sWql + o);
        }
#pragma unroll
        for (int njp = 0; njp < 2; njp++) {
            uint32_t o = rowoff + (n0 + njp * 16 + cshift) * 2;
            ldsm4t(Bh[njp], sT2h + o);
            ldsm4t(Bl[njp], sT2l + o);
        }
#pragma unroll
        for (int mi = 0; mi < 4; mi++)
#pragma unroll
            for (int nj = 0; nj < 4; nj++) {
                int njp = nj >> 1, odd = nj & 1;
                uint32_t bh0 = Bh[njp][odd], bh1 = Bh[njp][odd + 2];
                uint32_t bl0 = Bl[njp][odd], bl1 = Bl[njp][odd + 2];
                mma_bf16(acc3[mi][nj], Ah[mi], bh0, bh1);
                mma_bf16(acc3[mi][nj], Ah[mi], bl0, bl1);
                mma_bf16(acc3[mi][nj], Al[mi], bh0, bh1);
            }
    }
    float* Mp = g_Mpart + (size_t)(h * BB + b) * DD * DD;
#pragma unroll
    for (int mi = 0; mi < 4; mi++)
#pragma unroll
        for (int nj = 0; nj < 4; nj++) {
            int r = m0 + mi * 16 + g, cc = n0 + nj * 8 + t * 2;
            *(float2*)&Mp[r * DD + cc] =
                make_float2(acc3[mi][nj][0], acc3[mi][nj][1]);
            *(float2*)&Mp[(r + 8) * DD + cc] =
                make_float2(acc3[mi][nj][2], acc3[mi][nj][3]);
        }
}

// ==========================================================================
// Kernel C: sum Mparts over heads -> bf16 hi/lo [b][d][e].  grid (8, 32).
__global__ __launch_bounds__(256) void mconv() {
    const int b = blockIdx.y, ds = blockIdx.x;
    const int tid = threadIdx.x;
    const size_t base = (size_t)b * DD * DD + ds * 16 * DD;

    for (int i = tid; i < 512; i += 256) {
        float4 s = make_float4(0.f, 0.f, 0.f, 0.f);
#pragma unroll
        for (int h = 0; h < HH; h++) {
            float4 v = *(const float4*)(g_Mpart + (size_t)h * BB * DD * DD +
                                        base + i * 4);
            s.x += v.x; s.y += v.y; s.z += v.z; s.w += v.w;
        }
        float vv[4] = {s.x, s.y, s.z, s.w};
        __nv_bfloat16 hh[4], ll[4];
#pragma unroll
        for (int j = 0; j < 4; j++) {
            hh[j] = __float2bfloat16(vv[j]);
            ll[j] = __float2bfloat16(vv[j] - __bfloat162float(hh[j]));
        }
        *(uint2*)(g_Md_hi + base + i * 4) = *(uint2*)hh;
        *(uint2*)(g_Md_lo + base + i * 4) = *(uint2*)ll;
    }
}

// ==========================================================================
// Kernel O: out = x @ M, fp32 x read + inline conversion.  grid (16, 32).
// smem: staging fp32 [128][544B] (69632) | A hi/lo 2x[128][272] (69632)
//       | B hi/lo 2x[128][272] (69632).  Total 208896.
#define OSTR 272
#define OUT_SMEM_BYTES 208896
__global__ __launch_bounds__(256, 1) void out_mma(const float* __restrict__ x,
                                                  float* __restrict__ out) {
    extern __shared__ __align__(128) char sm[];
    uint32_t sb = smem_u32(sm);
    const int b = blockIdx.y, nblk = blockIdx.x * 128;
    const int tid = threadIdx.x, lane = tid & 31, wid = tid >> 5;
    const int m0 = (wid & 1) * 64, n0 = (wid >> 1) * 32;

    const uint32_t stg = sb;
    const uint32_t tAh = sb + 69632, tAl = sb + 104448;
    const uint32_t tBh = sb + 139264, tBl = sb + 173760 + 320;  // 174080

    const float* xb = x + ((size_t)b * NN + nblk) * DD;
    for (int i = tid; i < 4096; i += 256) {
        int row = i >> 5, seg = i & 31;
        CP_ASYNC16(stg + row * GFST + seg * 16, xb + (size_t)row * DD + seg * 4);
    }
    {
        const __nv_bfloat16* mh = g_Md_hi + (size_t)b * DD * DD;
        const __nv_bfloat16* ml = g_Md_lo + (size_t)b * DD * DD;
        for (int i = tid; i < 2048; i += 256) {
            int row = i >> 4, seg = i & 15;
            uint32_t o = row * OSTR + seg * 16;
            CP_ASYNC16(tBh + o, mh + row * DD + seg * 8);
            CP_ASYNC16(tBl + o, ml + row * DD + seg * 8);
        }
    }
    CP_ASYNC_COMMIT();
    CP_ASYNC_WAIT0();
    __syncthreads();
    // convert A
    for (int i = tid; i < 4096; i += 256) {
        int row = i >> 5, seg = i & 31;
        float4 v = *(const float4*)(sm + row * GFST + seg * 16);
        uint32_t h0, l0, h1, l1;
        packpair(v.x, v.y, h0, l0);
        packpair(v.z, v.w, h1, l1);
        *(uint2*)(sm + (tAh - sb) + row * OSTR + seg * 8) = make_uint2(h0, h1);
        *(uint2*)(sm + (tAl - sb) + row * OSTR + seg * 8) = make_uint2(l0, l1);
    }
    __syncthreads();

    float acc[4][4][4];
#pragma unroll
    for (int mi = 0; mi < 4; mi++)
#pragma unroll
        for (int nj = 0; nj < 4; nj++)
#pragma unroll
            for (int q = 0; q < 4; q++) acc[mi][nj][q] = 0.f;

    const int arow = lane & 15;
    const int kr = (lane & 7) + ((lane >> 4) << 3);
    const int cshift = ((lane >> 3) & 1) << 3;

#pragma unroll
    for (int ko = 0; ko < 128; ko += 16) {
        uint32_t Ah[4][4], Al[4][4], Bh[2][4], Bl[2][4];
        const int acolB = (ko + (lane >> 4) * 8) * 2;
#pragma unroll
        for (int mi = 0; mi < 4; mi++) {
            uint32_t o = (m0 + mi * 16 + arow) * OSTR + acolB;
            ldsm4(Ah[mi], tAh + o);
            ldsm4(Al[mi], tAl + o);
        }
        const uint32_t browoff = (ko + kr) * OSTR;
#pragma unroll
        for (int njp = 0; njp < 2; njp++) {
            uint32_t o = browoff + (n0 + njp * 16 + cshift) * 2;
            ldsm4t(Bh[njp], tBh + o);
            ldsm4t(Bl[njp], tBl + o);
        }
#pragma unroll
        for (int mi = 0; mi < 4; mi++)
#pragma unroll
            for (int nj = 0; nj < 4; nj++) {
                int njp = nj >> 1, odd = nj & 1;
                uint32_t bh0 = Bh[njp][odd], bh1 = Bh[njp][odd + 2];
                uint32_t bl0 = Bl[njp][odd], bl1 = Bl[njp][odd + 2];
                mma_bf16(acc[mi][nj], Ah[mi], bh0, bh1);
                mma_bf16(acc[mi][nj], Ah[mi], bl0, bl1);
                mma_bf16(acc[mi][nj], Al[mi], bh0, bh1);
            }
    }

    float* ob = out + ((size_t)b * NN + nblk) * DD;
    const int g = lane >> 2, t = lane & 3;
#pragma unroll
    for (int mi = 0; mi < 4; mi++)
#pragma unroll
        for (int nj = 0; nj < 4; nj++) {
            int r = m0 + mi * 16 + g, cc = n0 + nj * 8 + t * 2;
            *(float2*)&ob[r * DD + cc] =
                make_float2(acc[mi][nj][0], acc[mi][nj][1]);
            *(float2*)&ob[(r + 8) * DD + cc] =
                make_float2(acc[mi][nj][2], acc[mi][nj][3]);
        }
}

// ==========================================================================
extern "C" void kernel_launch(void* const* d_in, const int* in_sizes, int n_in,
                              void* d_out, int out_size) {
    const float* x  = (const float*)d_in[0];  // [32, 2048, 128]
    const float* Wk = (const float*)d_in[1];  // [8, 64, 128]
    const float* Wq = (const float*)d_in[2];  // [8, 64, 128]
    const float* Wv = (const float*)d_in[3];  // [8, 128, 128]
    float* out = (float*)d_out;               // [32, 2048, 128]

    cudaFuncSetAttribute(gram_mma, cudaFuncAttributeMaxDynamicSharedMemorySize,
                         GRAM_SMEM_BYTES);
    cudaFuncSetAttribute(mid_mma, cudaFuncAttributeMaxDynamicSharedMemorySize,
                         MID_SMEM_BYTES);
    cudaFuncSetAttribute(out_mma, cudaFuncAttributeMaxDynamicSharedMemorySize,
                         OUT_SMEM_BYTES);

    wconv<<<256, 256>>>(Wk, Wq, Wv);
    gram_mma<<<dim3(NSPLIT, 32), 256, GRAM_SMEM_BYTES>>>(x);
    sconv<<<dim3(4, 32), 256>>>();
    mid_mma<<<dim3(HH, 32), 256, MID_SMEM_BYTES>>>();
    mconv<<<dim3(8, 32), 256>>>();
    out_mma<<<dim3(16, 32), 256, OUT_SMEM_BYTES>>>(x, out);
}

// round 6
// speedup vs baseline: 2.7653x; 1.2086x over previous
#include <cuda_runtime.h>
#include <cuda_bf16.h>
#include <cstdint>

// Problem constants
#define BB 32
#define NN 2048
#define DD 128
#define HH 8
#define KQ 64
#define NSPLIT 8

// ------------------------------------------------------------------ scratch
__device__ float g_Spart[NSPLIT * BB * DD * DD];     // gram partials (fp32)
__device__ float g_Mpart[HH * BB * DD * DD];         // M partials per head
__device__ float g_M[BB * DD * DD];                  // summed M, tf32-rounded, [b][d][e]
__device__ __nv_bfloat16 g_S_hi[BB * DD * DD];       // S hi/lo, [b][d][d'] (for mid)
__device__ __nv_bfloat16 g_S_lo[BB * DD * DD];
__device__ __nv_bfloat16 g_Wk_hi[HH * KQ * DD];
__device__ __nv_bfloat16 g_Wk_lo[HH * KQ * DD];
__device__ __nv_bfloat16 g_Wq_hi[HH * KQ * DD];
__device__ __nv_bfloat16 g_Wq_lo[HH * KQ * DD];
__device__ __nv_bfloat16 g_Wv_hi[HH * DD * DD];
__device__ __nv_bfloat16 g_Wv_lo[HH * DD * DD];

// ------------------------------------------------------------------ helpers
__device__ __forceinline__ uint32_t smem_u32(const void* p) {
    uint32_t a;
    asm("{ .reg .u64 t; cvta.to.shared.u64 t, %1; cvt.u32.u64 %0, t; }"
        : "=r"(a) : "l"(p));
    return a;
}

#define CP_ASYNC16(saddr, gptr) \
    asm volatile("cp.async.cg.shared.global [%0], [%1], 16;" \
                 :: "r"(saddr), "l"(gptr) : "memory")
#define CP_ASYNC_COMMIT() asm volatile("cp.async.commit_group;" ::: "memory")
#define CP_ASYNC_WAIT0()  asm volatile("cp.async.wait_group 0;" ::: "memory")
#define CP_ASYNC_WAIT1()  asm volatile("cp.async.wait_group 1;" ::: "memory")

__device__ __forceinline__ void ldsm4(uint32_t* r, uint32_t addr) {
    asm volatile("ldmatrix.sync.aligned.m8n8.x4.shared.b16 {%0,%1,%2,%3}, [%4];"
                 : "=r"(r[0]), "=r"(r[1]), "=r"(r[2]), "=r"(r[3]) : "r"(addr));
}
__device__ __forceinline__ void ldsm4t(uint32_t* r, uint32_t addr) {
    asm volatile("ldmatrix.sync.aligned.m8n8.x4.trans.shared.b16 {%0,%1,%2,%3}, [%4];"
                 : "=r"(r[0]), "=r"(r[1]), "=r"(r[2]), "=r"(r[3]) : "r"(addr));
}

__device__ __forceinline__ void mma_bf16(float* d, const uint32_t* a,
                                         uint32_t b0, uint32_t b1) {
    asm volatile(
        "mma.sync.aligned.m16n8k16.row.col.f32.bf16.bf16.f32 "
        "{%0,%1,%2,%3}, {%4,%5,%6,%7}, {%8,%9}, {%0,%1,%2,%3};"
        : "+f"(d[0]), "+f"(d[1]), "+f"(d[2]), "+f"(d[3])
        : "r"(a[0]), "r"(a[1]), "r"(a[2]), "r"(a[3]), "r"(b0), "r"(b1));
}

__device__ __forceinline__ void mma_tf32(float* d, const uint32_t* a,
                                         uint32_t b0, uint32_t b1) {
    asm volatile(
        "mma.sync.aligned.m16n8k8.row.col.f32.tf32.tf32.f32 "
        "{%0,%1,%2,%3}, {%4,%5,%6,%7}, {%8,%9}, {%0,%1,%2,%3};"
        : "+f"(d[0]), "+f"(d[1]), "+f"(d[2]), "+f"(d[3])
        : "r"(a[0]), "r"(a[1]), "r"(a[2]), "r"(a[3]), "r"(b0), "r"(b1));
}

__device__ __forceinline__ uint32_t f2tf(float f) {
    uint32_t r;
    asm("cvt.rna.tf32.f32 %0, %1;" : "=r"(r) : "f"(f));
    return r;
}

__device__ __forceinline__ void packpair(float v0, float v1,
                                         uint32_t& hi, uint32_t& lo) {
    __nv_bfloat16 h0 = __float2bfloat16(v0);
    __nv_bfloat16 h1 = __float2bfloat16(v1);
    __nv_bfloat16 l0 = __float2bfloat16(v0 - __bfloat162float(h0));
    __nv_bfloat16 l1 = __float2bfloat16(v1 - __bfloat162float(h1));
    hi = (uint32_t)*(uint16_t*)&h0 | ((uint32_t)*(uint16_t*)&h1 << 16);
    lo = (uint32_t)*(uint16_t*)&l0 | ((uint32_t)*(uint16_t*)&l1 << 16);
}

// ==========================================================================
// Kernel W: convert Wk, Wq, Wv to hi/lo bf16 (for mid)
__global__ __launch_bounds__(256) void wconv(const float* __restrict__ Wk,
                                             const float* __restrict__ Wq,
                                             const float* __restrict__ Wv) {
    int i4 = blockIdx.x * 256 + threadIdx.x;   // 0..65535
    const float* src;
    __nv_bfloat16 *dh, *dl;
    int off;
    if (i4 < 16384)      { src = Wk; dh = g_Wk_hi; dl = g_Wk_lo; off = i4; }
    else if (i4 < 32768) { src = Wq; dh = g_Wq_hi; dl = g_Wq_lo; off = i4 - 16384; }
    else                 { src = Wv; dh = g_Wv_hi; dl = g_Wv_lo; off = i4 - 32768; }
    float4 v = ((const float4*)src)[off];
    float vv[4] = {v.x, v.y, v.z, v.w};
    __nv_bfloat16 h[4], l[4];
#pragma unroll
    for (int j = 0; j < 4; j++) {
        h[j] = __float2bfloat16(vv[j]);
        l[j] = __float2bfloat16(vv[j] - __bfloat162float(h[j]));
    }
    *(uint2*)(dh + (size_t)off * 4) = *(uint2*)h;
    *(uint2*)(dl + (size_t)off * 4) = *(uint2*)l;
}

// ==========================================================================
// Kernel G: Gram partials via tf32 mma (single pass).
// grid (NSPLIT=8, 32), 256 threads.  K=256 per CTA, 4 chunks of 64 n-rows.
// smem: SG staging 2 x [64 n][132 f] fp32 (cp.async dest, stride 528B)
//       X' tile 1 x [128 d][68 f] fp32 tf32-rounded (transposed, stride 272B)
#define GRAM_SMEM_BYTES (2 * 33792 + 34816)   // 102400
__global__ __launch_bounds__(256, 1) void gram_mma(const float* __restrict__ x) {
    extern __shared__ __align__(128) char sm[];
    uint32_t sb = smem_u32(sm);
    const int b = blockIdx.y, split = blockIdx.x;
    const int nbase = split * 256;
    const int tid = threadIdx.x, lane = tid & 31, wid = tid >> 5;
    const int m0 = (wid & 1) * 64, n0 = (wid >> 1) * 32;
    const float* xb = x + (size_t)b * NN * DD;

    const uint32_t Xp = sb + 67584;    // X' tile base

    float acc[4][4][4];
#pragma unroll
    for (int mi = 0; mi < 4; mi++)
#pragma unroll
        for (int nj = 0; nj < 4; nj++)
#pragma unroll
            for (int q = 0; q < 4; q++) acc[mi][nj][q] = 0.f;

#define GRAM_ISSUE(c)                                                          \
    do {                                                                       \
        int nc_ = nbase + (c) * 64;                                            \
        uint32_t stg_ = sb + ((c) & 1) * 33792;                                \
        for (int i = tid; i < 2048; i += 256) {                                \
            int row = i >> 5, seg = i & 31;                                    \
            CP_ASYNC16(stg_ + row * 528 + seg * 16,                            \
                       xb + (size_t)(nc_ + row) * DD + seg * 4);               \
        }                                                                      \
        CP_ASYNC_COMMIT();                                                     \
    } while (0)

    // ldmatrix lane address components (tf32-on-b16 trick)
    const int a_row = lane & 15, a_cg = lane >> 4;               // A x4
    const int b_row = (lane & 7) + ((lane >> 4) << 3);           // B x4 (2 frags)
    const int b_cg = (lane >> 3) & 1;

    GRAM_ISSUE(0);
    for (int c = 0; c < 4; c++) {
        if (c + 1 < 4) { GRAM_ISSUE(c + 1); CP_ASYNC_WAIT1(); }
        else           { CP_ASYNC_WAIT0(); }
        __syncthreads();
        // transpose + tf32-round: SG[c&1] [n][d] -> X' [d][n]
        {
            const float* SGp = (const float*)(sm + (c & 1) * 33792);
            float* XpF = (float*)(sm + 67584);
#pragma unroll
            for (int half = 0; half < 2; half++) {
                int row = half * 32 + lane;          // local n
#pragma unroll
                for (int s = 0; s < 4; s++) {
                    int seg = wid * 4 + s;           // d group
                    float4 v = *(const float4*)(SGp + row * 132 + seg * 4);
                    XpF[(seg * 4 + 0) * 68 + row] = __uint_as_float(f2tf(v.x));
                    XpF[(seg * 4 + 1) * 68 + row] = __uint_as_float(f2tf(v.y));
                    XpF[(seg * 4 + 2) * 68 + row] = __uint_as_float(f2tf(v.z));
                    XpF[(seg * 4 + 3) * 68 + row] = __uint_as_float(f2tf(v.w));
                }
            }
        }
        __syncthreads();
#pragma unroll
        for (int ko = 0; ko < 64; ko += 8) {
            uint32_t A[4][4], B[2][4];
#pragma unroll
            for (int mi = 0; mi < 4; mi++)
                ldsm4(A[mi], Xp + (m0 + mi * 16 + a_row) * 272 +
                             (ko + 4 * a_cg) * 4);
#pragma unroll
            for (int njp = 0; njp < 2; njp++)
                ldsm4(B[njp], Xp + (n0 + njp * 16 + b_row) * 272 +
                              (ko + 4 * b_cg) * 4);
#pragma unroll
            for (int mi = 0; mi < 4; mi++)
#pragma unroll
                for (int nj = 0; nj < 4; nj++)
                    mma_tf32(acc[mi][nj], A[mi],
                             B[nj >> 1][(nj & 1) * 2], B[nj >> 1][(nj & 1) * 2 + 1]);
        }
        __syncthreads();
    }

    float* Sp = g_Spart + (size_t)(split * BB + b) * (DD * DD);
    const int g = lane >> 2, t = lane & 3;
#pragma unroll
    for (int mi = 0; mi < 4; mi++)
#pragma unroll
        for (int nj = 0; nj < 4; nj++) {
            int r = m0 + mi * 16 + g, cc = n0 + nj * 8 + t * 2;
            *(float2*)&Sp[r * DD + cc] =
                make_float2(acc[mi][nj][0], acc[mi][nj][1]);
            *(float2*)&Sp[(r + 8) * DD + cc] =
                make_float2(acc[mi][nj][2], acc[mi][nj][3]);
        }
}

// ==========================================================================
// Kernel S: sum Spart -> S hi/lo bf16 [b][d][d'] (for mid).  grid (4, 32).
__global__ __launch_bounds__(256) void sconv() {
    const int b = blockIdx.y, ds = blockIdx.x;
    const int tid = threadIdx.x;
    const size_t base = (size_t)b * DD * DD + ds * 32 * DD;

    for (int i = tid; i < 1024; i += 256) {
        float4 s = make_float4(0.f, 0.f, 0.f, 0.f);
#pragma unroll
        for (int p = 0; p < NSPLIT; p++) {
            float4 v = *(const float4*)(g_Spart + (size_t)p * BB * DD * DD +
                                        base + i * 4);
            s.x += v.x; s.y += v.y; s.z += v.z; s.w += v.w;
        }
        float vv[4] = {s.x, s.y, s.z, s.w};
        __nv_bfloat16 hh[4], ll[4];
#pragma unroll
        for (int j = 0; j < 4; j++) {
            hh[j] = __float2bfloat16(vv[j]);
            ll[j] = __float2bfloat16(vv[j] - __bfloat162float(hh[j]));
        }
        *(uint2*)(g_S_hi + base + i * 4) = *(uint2*)hh;
        *(uint2*)(g_S_lo + base + i * 4) = *(uint2*)ll;
    }
}

// ==========================================================================
// Kernel M: split-bf16 tensor-core mid (verbatim R5).  grid (8, 32), 256 thr.
#define GSTR 272
#define MID_SMEM_BYTES 208896
__global__ __launch_bounds__(256, 1) void mid_mma() {
    extern __shared__ __align__(128) char sm[];
    uint32_t sb = smem_u32(sm);
    const int h = blockIdx.x, b = blockIdx.y;
    const int tid = threadIdx.x, lane = tid & 31, wid = tid >> 5;

    const uint32_t sWkh = sb,            sWkl = sb + 17408;
    const uint32_t sSh  = sb + 34816,    sSl  = sb + 69632;
    const uint32_t sWqh = sb + 34816,    sWql = sb + 52224;
    const uint32_t sT2h = sb + 69632,    sT2l = sb + 87040;
    const uint32_t sWvh = sb + 104448,   sWvl = sb + 139264;
    const uint32_t sT1h = sb + 174080,   sT1l = sb + 191488;

    {
        const __nv_bfloat16* wkh = g_Wk_hi + (size_t)h * KQ * DD;
        const __nv_bfloat16* wkl = g_Wk_lo + (size_t)h * KQ * DD;
        for (int i = tid; i < 1024; i += 256) {
            int row = i >> 4, seg = i & 15;
            uint32_t o = row * GSTR + seg * 16;
            CP_ASYNC16(sWkh + o, wkh + row * DD + seg * 8);
            CP_ASYNC16(sWkl + o, wkl + row * DD + seg * 8);
        }
        const __nv_bfloat16* ssh = g_S_hi + (size_t)b * DD * DD;
        const __nv_bfloat16* ssl = g_S_lo + (size_t)b * DD * DD;
        for (int i = tid; i < 2048; i += 256) {
            int row = i >> 4, seg = i & 15;
            uint32_t o = row * GSTR + seg * 16;
            CP_ASYNC16(sSh + o, ssh + row * DD + seg * 8);
            CP_ASYNC16(sSl + o, ssl + row * DD + seg * 8);
        }
        CP_ASYNC_COMMIT();
    }
    {
        const __nv_bfloat16* wvh = g_Wv_hi + (size_t)h * DD * DD;
        const __nv_bfloat16* wvl = g_Wv_lo + (size_t)h * DD * DD;
        for (int i = tid; i < 2048; i += 256) {
            int row = i >> 4, seg = i & 15;
            uint32_t o = row * GSTR + seg * 16;
            CP_ASYNC16(sWvh + o, wvh + row * DD + seg * 8);
            CP_ASYNC16(sWvl + o, wvl + row * DD + seg * 8);
        }
        CP_ASYNC_COMMIT();
    }

    const int kr = (lane & 7) + ((lane >> 4) << 3);
    const int cshift = ((lane >> 3) & 1) << 3;
    const int arow = lane & 15;
    const int g = lane >> 2, t = lane & 3;

    const int m0s = (wid & 3) * 16, n0s = (wid >> 2) * 64;
    float acc1[8][4];
#pragma unroll
    for (int nj = 0; nj < 8; nj++)
#pragma unroll
        for (int q = 0; q < 4; q++) acc1[nj][q] = 0.f;

    CP_ASYNC_WAIT1();
    __syncthreads();
#pragma unroll
    for (int ko = 0; ko < 128; ko += 16) {
        uint32_t Ah[4], Al[4], Bh[4][4], Bl[4][4];
        const int acolB = (ko + (lane >> 4) * 8) * 2;
        {
            uint32_t o = (m0s + arow) * GSTR + acolB;
            ldsm4(Ah, sWkh + o);
            ldsm4(Al, sWkl + o);
        }
        const uint32_t rowoff = (ko + kr) * GSTR;
#pragma unroll
        for (int njp = 0; njp < 4; njp++) {
            uint32_t o = rowoff + (n0s + njp * 16 + cshift) * 2;
            ldsm4t(Bh[njp], sSh + o);
            ldsm4t(Bl[njp], sSl + o);
        }
#pragma unroll
        for (int nj = 0; nj < 8; nj++) {
            int njp = nj >> 1, odd = nj & 1;
            uint32_t bh0 = Bh[njp][odd], bh1 = Bh[njp][odd + 2];
            uint32_t bl0 = Bl[njp][odd], bl1 = Bl[njp][odd + 2];
            mma_bf16(acc1[nj], Ah, bh0, bh1);
            mma_bf16(acc1[nj], Ah, bl0, bl1);
            mma_bf16(acc1[nj], Al, bh0, bh1);
        }
    }
    __syncthreads();

#pragma unroll
    for (int nj = 0; nj < 8; nj++) {
        uint32_t h0, l0, h1, l1;
        int cc = n0s + nj * 8 + t * 2;
        packpair(acc1[nj][0], acc1[nj][1], h0, l0);
        packpair(acc1[nj][2], acc1[nj][3], h1, l1);
        *(uint32_t*)(sm + (sT1h - sb) + (m0s + g) * GSTR + cc * 2) = h0;
        *(uint32_t*)(sm + (sT1l - sb) + (m0s + g) * GSTR + cc * 2) = l0;
        *(uint32_t*)(sm + (sT1h - sb) + (m0s + g + 8) * GSTR + cc * 2) = h1;
        *(uint32_t*)(sm + (sT1l - sb) + (m0s + g + 8) * GSTR + cc * 2) = l1;
    }
    {
        const __nv_bfloat16* wqh = g_Wq_hi + (size_t)h * KQ * DD;
        const __nv_bfloat16* wql = g_Wq_lo + (size_t)h * KQ * DD;
        for (int i = tid; i < 1024; i += 256) {
            int row = i >> 4, seg = i & 15;
            uint32_t o = row * GSTR + seg * 16;
            CP_ASYNC16(sWqh + o, wqh + row * DD + seg * 8);
            CP_ASYNC16(sWql + o, wql + row * DD + seg * 8);
        }
        CP_ASYNC_COMMIT();
    }
    CP_ASYNC_WAIT1();
    __syncthreads();

    float acc2[8][4];
#pragma unroll
    for (int nj = 0; nj < 8; nj++)
#pragma unroll
        for (int q = 0; q < 4; q++) acc2[nj][q] = 0.f;
#pragma unroll
    for (int ko = 0; ko < 128; ko += 16) {
        uint32_t Ah[4], Al[4], Bh[4][4], Bl[4][4];
        const int acolB = (ko + (lane >> 4) * 8) * 2;
        {
            uint32_t o = (m0s + arow) * GSTR + acolB;
            ldsm4(Ah, sT1h + o);
            ldsm4(Al, sT1l + o);
        }
#pragma unroll
        for (int njp = 0; njp < 4; njp++) {
            uint32_t o = (n0s + njp * 16 + arow) * GSTR + acolB;
            ldsm4(Bh[njp], sWvh + o);
            ldsm4(Bl[njp], sWvl + o);
        }
#pragma unroll
        for (int nj = 0; nj < 8; nj++) {
            int njp = nj >> 1, odd = nj & 1;
            uint32_t bh0 = Bh[njp][odd], bh1 = Bh[njp][odd + 2];
            uint32_t bl0 = Bl[njp][odd], bl1 = Bl[njp][odd + 2];
            mma_bf16(acc2[nj], Ah, bh0, bh1);
            mma_bf16(acc2[nj], Ah, bl0, bl1);
            mma_bf16(acc2[nj], Al, bh0, bh1);
        }
    }
#pragma unroll
    for (int nj = 0; nj < 8; nj++) {
        uint32_t h0, l0, h1, l1;
        int cc = n0s + nj * 8 + t * 2;
        packpair(acc2[nj][0], acc2[nj][1], h0, l0);
        packpair(acc2[nj][2], acc2[nj][3], h1, l1);
        *(uint32_t*)(sm + (sT2h - sb) + (m0s + g) * GSTR + cc * 2) = h0;
        *(uint32_t*)(sm + (sT2l - sb) + (m0s + g) * GSTR + cc * 2) = l0;
        *(uint32_t*)(sm + (sT2h - sb) + (m0s + g + 8) * GSTR + cc * 2) = h1;
        *(uint32_t*)(sm + (sT2l - sb) + (m0s + g + 8) * GSTR + cc * 2) = l1;
    }
    CP_ASYNC_WAIT0();
    __syncthreads();

    const int m0 = (wid & 1) * 64, n0 = (wid >> 1) * 32;
    float acc3[4][4][4];
#pragma unroll
    for (int mi = 0; mi < 4; mi++)
#pragma unroll
        for (int nj = 0; nj < 4; nj++)
#pragma unroll
            for (int q = 0; q < 4; q++) acc3[mi][nj][q] = 0.f;
#pragma unroll
    for (int ko = 0; ko < 64; ko += 16) {
        uint32_t Ah[4][4], Al[4][4], Bh[2][4], Bl[2][4];
        const uint32_t rowoff = (ko + kr) * GSTR;
#pragma unroll
        for (int mi = 0; mi < 4; mi++) {
            uint32_t o = rowoff + (m0 + mi * 16 + cshift) * 2;
            ldsm4t(Ah[mi], sWqh + o);
            ldsm4t(Al[mi], sWql + o);
        }
#pragma unroll
        for (int njp = 0; njp < 2; njp++) {
            uint32_t o = rowoff + (n0 + njp * 16 + cshift) * 2;
            ldsm4t(Bh[njp], sT2h + o);
            ldsm4t(Bl[njp], sT2l + o);
        }
#pragma unroll
        for (int mi = 0; mi < 4; mi++)
#pragma unroll
            for (int nj = 0; nj < 4; nj++) {
                int njp = nj >> 1, odd = nj & 1;
                uint32_t bh0 = Bh[njp][odd], bh1 = Bh[njp][odd + 2];
                uint32_t bl0 = Bl[njp][odd], bl1 = Bl[njp][odd + 2];
                mma_bf16(acc3[mi][nj], Ah[mi], bh0, bh1);
                mma_bf16(acc3[mi][nj], Ah[mi], bl0, bl1);
                mma_bf16(acc3[mi][nj], Al[mi], bh0, bh1);
            }
    }
    float* Mp = g_Mpart + (size_t)(h * BB + b) * DD * DD;
#pragma unroll
    for (int mi = 0; mi < 4; mi++)
#pragma unroll
        for (int nj = 0; nj < 4; nj++) {
            int r = m0 + mi * 16 + g, cc = n0 + nj * 8 + t * 2;
            *(float2*)&Mp[r * DD + cc] =
                make_float2(acc3[mi][nj][0], acc3[mi][nj][1]);
            *(float2*)&Mp[(r + 8) * DD + cc] =
                make_float2(acc3[mi][nj][2], acc3[mi][nj][3]);
        }
}

// ==========================================================================
// Kernel C: sum Mparts over heads -> tf32-rounded fp32 [b][d][e].  grid (8,32).
__global__ __launch_bounds__(256) void mconv() {
    const int b = blockIdx.y, ds = blockIdx.x;
    const int tid = threadIdx.x;
    const size_t base = (size_t)b * DD * DD + ds * 16 * DD;

    for (int i = tid; i < 512; i += 256) {
        float4 s = make_float4(0.f, 0.f, 0.f, 0.f);
#pragma unroll
        for (int h = 0; h < HH; h++) {
            float4 v = *(const float4*)(g_Mpart + (size_t)h * BB * DD * DD +
                                        base + i * 4);
            s.x += v.x; s.y += v.y; s.z += v.z; s.w += v.w;
        }
        float4 o;
        o.x = __uint_as_float(f2tf(s.x));
        o.y = __uint_as_float(f2tf(s.y));
        o.z = __uint_as_float(f2tf(s.z));
        o.w = __uint_as_float(f2tf(s.w));
        *(float4*)(g_M + base + i * 4) = o;
    }
}

// ==========================================================================
// Kernel O: out = x @ M via tf32 mma (single pass).  grid (16, 32), 256 thr.
// smem: x tile [128 n][132 f] (528B rows, ldmatrix A, cvt in place)
//       M tile [128 d][136 f] (544B rows, scalar-LDS B, pre-rounded)
#define OUT_SMEM_BYTES (67584 + 69632)   // 137216
__global__ __launch_bounds__(256, 1) void out_mma(const float* __restrict__ x,
                                                  float* __restrict__ out) {
    extern __shared__ __align__(128) char sm[];
    uint32_t sb = smem_u32(sm);
    const int b = blockIdx.y, nblk = blockIdx.x * 128;
    const int tid = threadIdx.x, lane = tid & 31, wid = tid >> 5;
    const int m0 = (wid & 1) * 64, n0 = (wid >> 1) * 32;

    const uint32_t tA = sb;            // x tile
    const uint32_t tB = sb + 67584;    // M tile
    float* tBf = (float*)(sm + 67584);

    const float* xb = x + ((size_t)b * NN + nblk) * DD;
    for (int i = tid; i < 4096; i += 256) {
        int row = i >> 5, seg = i & 31;
        CP_ASYNC16(tA + row * 528 + seg * 16, xb + (size_t)row * DD + seg * 4);
    }
    {
        const float* mb = g_M + (size_t)b * DD * DD;
        for (int i = tid; i < 4096; i += 256) {
            int row = i >> 5, seg = i & 31;
            CP_ASYNC16(tB + row * 544 + seg * 16, mb + (size_t)row * DD + seg * 4);
        }
    }
    CP_ASYNC_COMMIT();
    CP_ASYNC_WAIT0();
    __syncthreads();
    // tf32-round x in place
    {
        float* tAf = (float*)sm;
        for (int i = tid; i < 4096; i += 256) {
            int row = i >> 5, seg = i & 31;
            float4 v = *(float4*)(tAf + row * 132 + seg * 4);
            v.x = __uint_as_float(f2tf(v.x));
            v.y = __uint_as_float(f2tf(v.y));
            v.z = __uint_as_float(f2tf(v.z));
            v.w = __uint_as_float(f2tf(v.w));
            *(float4*)(tAf + row * 132 + seg * 4) = v;
        }
    }
    __syncthreads();

    float acc[4][4][4];
#pragma unroll
    for (int mi = 0; mi < 4; mi++)
#pragma unroll
        for (int nj = 0; nj < 4; nj++)
#pragma unroll
            for (int q = 0; q < 4; q++) acc[mi][nj][q] = 0.f;

    const int a_row = lane & 15, a_cg = lane >> 4;
    const int g = lane >> 2, t = lane & 3;

#pragma unroll
    for (int ko = 0; ko < 128; ko += 8) {
        uint32_t A[4][4];
#pragma unroll
        for (int mi = 0; mi < 4; mi++)
            ldsm4(A[mi], tA + (m0 + mi * 16 + a_row) * 528 +
                         (ko + 4 * a_cg) * 4);
        uint32_t B0[4], B1[4];
#pragma unroll
        for (int nj = 0; nj < 4; nj++) {
            int col = n0 + nj * 8 + g;
            B0[nj] = __float_as_uint(tBf[(ko + t) * 136 + col]);
            B1[nj] = __float_as_uint(tBf[(ko + t + 4) * 136 + col]);
        }
#pragma unroll
        for (int mi = 0; mi < 4; mi++)
#pragma unroll
            for (int nj = 0; nj < 4; nj++)
                mma_tf32(acc[mi][nj], A[mi], B0[nj], B1[nj]);
    }

    float* ob = out + ((size_t)b * NN + nblk) * DD;
#pragma unroll
    for (int mi = 0; mi < 4; mi++)
#pragma unroll
        for (int nj = 0; nj < 4; nj++) {
            int r = m0 + mi * 16 + g, cc = n0 + nj * 8 + t * 2;
            *(float2*)&ob[r * DD + cc] =
                make_float2(acc[mi][nj][0], acc[mi][nj][1]);
            *(float2*)&ob[(r + 8) * DD + cc] =
                make_float2(acc[mi][nj][2], acc[mi][nj][3]);
        }
}

// ==========================================================================
extern "C" void kernel_launch(void* const* d_in, const int* in_sizes, int n_in,
                              void* d_out, int out_size) {
    const float* x  = (const float*)d_in[0];  // [32, 2048, 128]
    const float* Wk = (const float*)d_in[1];  // [8, 64, 128]
    const float* Wq = (const float*)d_in[2];  // [8, 64, 128]
    const float* Wv = (const float*)d_in[3];  // [8, 128, 128]
    float* out = (float*)d_out;               // [32, 2048, 128]

    cudaFuncSetAttribute(gram_mma, cudaFuncAttributeMaxDynamicSharedMemorySize,
                         GRAM_SMEM_BYTES);
    cudaFuncSetAttribute(mid_mma, cudaFuncAttributeMaxDynamicSharedMemorySize,
                         MID_SMEM_BYTES);
    cudaFuncSetAttribute(out_mma, cudaFuncAttributeMaxDynamicSharedMemorySize,
                         OUT_SMEM_BYTES);

    wconv<<<256, 256>>>(Wk, Wq, Wv);
    gram_mma<<<dim3(NSPLIT, 32), 256, GRAM_SMEM_BYTES>>>(x);
    sconv<<<dim3(4, 32), 256>>>();
    mid_mma<<<dim3(HH, 32), 256, MID_SMEM_BYTES>>>();
    mconv<<<dim3(8, 32), 256>>>();
    out_mma<<<dim3(16, 32), 256, OUT_SMEM_BYTES>>>(x, out);
}